// round 1
// baseline (speedup 1.0000x reference)
#include <cuda_runtime.h>
#include <cstddef>

// ---------------- problem constants ----------------
#define TSTEPS 8
#define BATCH  64
#define CC     3
#define NWIN   232
#define HH     64
#define WW     64
#define CHUNK  29
#define DPP    13
#define HP     32
#define WP     32
#define INDIM  1024      // HP*WP
#define H0     512
#define H1     512
#define H2     256
#define CD     39        // CC*DPP
#define FEAT   9984      // CD*H2
#define NCLS   4
#define MROWS  (BATCH*CD)        // 2496
#define MALL   (TSTEPS*MROWS)    // 19968
#define BETA   0.9f

// ---------------- scratch (static device memory; no allocations) -----------
__device__ float g_pooled[(size_t)MALL * INDIM];  // 19968 x 1024
__device__ float g_cur1 [(size_t)MALL * H0];      // 19968 x 512 (all timesteps)
__device__ float g_s1   [(size_t)MROWS * H0];
__device__ float g_s2   [(size_t)MROWS * H1];
__device__ float g_s3   [(size_t)MROWS * H2];
__device__ float g_min  [(size_t)MROWS * H0];
__device__ float g_mh1  [(size_t)MROWS * H1];
__device__ float g_mh2  [(size_t)MROWS * H2];
__device__ float g_mout [(size_t)BATCH * NCLS];

// ---------------- avg-pool3d (4,2,2)/(2,2,2) VALID, fused reshape ----------
// output layout: [t][b][cd][hp*32+wp] with cd = c*13+dp  == A matrix 19968x1024
__global__ void pool_kernel(const float* __restrict__ x) {
    int idx = blockIdx.x * blockDim.x + threadIdx.x;
    if (idx >= MALL * INDIM) return;
    int hw = idx & (INDIM - 1);
    int r  = idx >> 10;            // (t,b,cd)
    int cd = r % CD;
    int tb = r / CD;
    int b  = tb % BATCH;
    int t  = tb / BATCH;
    int c  = cd / DPP;
    int dp = cd % DPP;
    int hp = hw >> 5;
    int wp = hw & 31;
    int d0 = t * CHUNK + 2 * dp;
    const float* base = x + (((size_t)b * CC + c) * NWIN) * (HH * WW)
                          + (size_t)(2 * hp) * WW + (size_t)(2 * wp);
    float s = 0.f;
#pragma unroll
    for (int kd = 0; kd < 4; kd++) {
        const float* p = base + (size_t)(d0 + kd) * (HH * WW);
        float2 r0 = *(const float2*)(p);
        float2 r1 = *(const float2*)(p + WW);
        s += (r0.x + r0.y) + (r1.x + r1.y);
    }
    g_pooled[idx] = s * (1.0f / 16.0f);
}

// ---------------- tiled fp32 GEMM: C[m][n] = A[m][:] . B[n][:] + bias[n] ---
// A: MxK row-major, Bw: NxK row-major. Optional fused LIF epilogue
// (reset-by-subtraction, snntorch Leaky) writing spikes + updating mem.
template<int BM, int BN, int BK, int TM, int TN, bool LIF>
__global__ void sgemm_kernel(const float* __restrict__ A,
                             const float* __restrict__ Bw,
                             const float* __restrict__ bias,
                             float* __restrict__ Cout,
                             float* __restrict__ mem,
                             int M, int N, int K, float thr) {
    constexpr int THREADS = (BM / TM) * (BN / TN);
    __shared__ float As[BK][BM + 4];
    __shared__ float Bs[BK][BN + 4];

    const int tid = threadIdx.x;
    const int tx  = tid % (BN / TN);
    const int ty  = tid / (BN / TN);
    const int bm  = blockIdx.y * BM;
    const int bn  = blockIdx.x * BN;

    float acc[TM][TN];
#pragma unroll
    for (int i = 0; i < TM; i++)
#pragma unroll
        for (int j = 0; j < TN; j++) acc[i][j] = 0.f;

    constexpr int K4       = BK / 4;         // float4 columns per row
    constexpr int ROWS_PER = THREADS / K4;   // rows loaded per pass
    const int lrow = tid / K4;
    const int lcol = (tid % K4) * 4;

    for (int kt = 0; kt < K; kt += BK) {
#pragma unroll
        for (int i = 0; i < BM; i += ROWS_PER) {
            float4 v = *(const float4*)(A + (size_t)(bm + lrow + i) * K + kt + lcol);
            As[lcol + 0][lrow + i] = v.x;
            As[lcol + 1][lrow + i] = v.y;
            As[lcol + 2][lrow + i] = v.z;
            As[lcol + 3][lrow + i] = v.w;
        }
#pragma unroll
        for (int i = 0; i < BN; i += ROWS_PER) {
            float4 v = *(const float4*)(Bw + (size_t)(bn + lrow + i) * K + kt + lcol);
            Bs[lcol + 0][lrow + i] = v.x;
            Bs[lcol + 1][lrow + i] = v.y;
            Bs[lcol + 2][lrow + i] = v.z;
            Bs[lcol + 3][lrow + i] = v.w;
        }
        __syncthreads();
#pragma unroll
        for (int k = 0; k < BK; k++) {
            float ar[TM], br[TN];
#pragma unroll
            for (int i = 0; i < TM; i++) ar[i] = As[k][ty * TM + i];
#pragma unroll
            for (int j = 0; j < TN; j++) br[j] = Bs[k][tx * TN + j];
#pragma unroll
            for (int i = 0; i < TM; i++)
#pragma unroll
                for (int j = 0; j < TN; j++) acc[i][j] += ar[i] * br[j];
        }
        __syncthreads();
    }

#pragma unroll
    for (int i = 0; i < TM; i++) {
        const int m = bm + ty * TM + i;
#pragma unroll
        for (int j = 0; j < TN; j++) {
            const int n = bn + tx * TN + j;
            const size_t o = (size_t)m * N + n;
            float v = acc[i][j] + bias[n];
            if (LIF) {
                float mo = mem[o];
                float mn = BETA * mo + v - (mo > thr ? thr : 0.f);
                mem[o] = mn;
                Cout[o] = (mn - thr) > 0.f ? 1.f : 0.f;
            } else {
                Cout[o] = v;
            }
        }
    }
}

// ---------------- elementwise LIF for layer 1 (cur precomputed) ------------
__global__ void lif_kernel(const float* __restrict__ cur,
                           float* __restrict__ mem,
                           float* __restrict__ spk, int n, float thr) {
    int i = blockIdx.x * blockDim.x + threadIdx.x;
    if (i >= n) return;
    float mo = mem[i];
    float mn = BETA * mo + cur[i] - (mo > thr ? thr : 0.f);
    mem[i] = mn;
    spk[i] = (mn - thr) > 0.f ? 1.f : 0.f;
}

// ---------------- readout: 64 x (9984 -> 4) + LIF(thr=1) ------------------
__global__ void fcout_kernel(const float* __restrict__ s3,
                             const float* __restrict__ Wout,
                             const float* __restrict__ bout,
                             float* __restrict__ mout,
                             float* __restrict__ out_t) {
    const int b   = blockIdx.x;
    const int tid = threadIdx.x;   // 256
    const float* sp = s3 + (size_t)b * FEAT;
    float a0 = 0.f, a1 = 0.f, a2 = 0.f, a3 = 0.f;
    for (int k = tid; k < FEAT; k += 256) {
        float s = sp[k];
        if (s != 0.f) {   // spikes are exactly 0/1: add the weight
            a0 += Wout[0 * FEAT + k];
            a1 += Wout[1 * FEAT + k];
            a2 += Wout[2 * FEAT + k];
            a3 += Wout[3 * FEAT + k];
        }
    }
    __shared__ float red[4][256];
    red[0][tid] = a0; red[1][tid] = a1; red[2][tid] = a2; red[3][tid] = a3;
    __syncthreads();
    for (int st = 128; st > 0; st >>= 1) {
        if (tid < st) {
#pragma unroll
            for (int n = 0; n < 4; n++) red[n][tid] += red[n][tid + st];
        }
        __syncthreads();
    }
    if (tid < NCLS) {
        float cur = red[tid][0] + bout[tid];
        float mo  = mout[b * NCLS + tid];
        float mn  = BETA * mo + cur - (mo > 1.0f ? 1.0f : 0.f);
        mout[b * NCLS + tid] = mn;
        out_t[b * NCLS + tid] = (mn - 1.0f) > 0.f ? 1.f : 0.f;
    }
}

// ---------------- host orchestration (graph-capturable) --------------------
extern "C" void kernel_launch(void* const* d_in, const int* in_sizes, int n_in,
                              void* d_out, int out_size) {
    const float* x     = (const float*)d_in[0];
    const float* W_in  = (const float*)d_in[1];
    const float* b_in  = (const float*)d_in[2];
    const float* W_h1  = (const float*)d_in[3];
    const float* b_h1  = (const float*)d_in[4];
    const float* W_h2  = (const float*)d_in[5];
    const float* b_h2  = (const float*)d_in[6];
    const float* W_out = (const float*)d_in[7];
    const float* b_out = (const float*)d_in[8];
    float* out = (float*)d_out;

    float *pooled, *cur1, *s1, *s2, *s3, *m_in, *m_h1, *m_h2, *m_out;
    cudaGetSymbolAddress((void**)&pooled, g_pooled);
    cudaGetSymbolAddress((void**)&cur1,   g_cur1);
    cudaGetSymbolAddress((void**)&s1,     g_s1);
    cudaGetSymbolAddress((void**)&s2,     g_s2);
    cudaGetSymbolAddress((void**)&s3,     g_s3);
    cudaGetSymbolAddress((void**)&m_in,   g_min);
    cudaGetSymbolAddress((void**)&m_h1,   g_mh1);
    cudaGetSymbolAddress((void**)&m_h2,   g_mh2);
    cudaGetSymbolAddress((void**)&m_out,  g_mout);

    // zero membrane state (must be deterministic per call)
    cudaMemsetAsync(m_in,  0, (size_t)MROWS * H0 * sizeof(float));
    cudaMemsetAsync(m_h1,  0, (size_t)MROWS * H1 * sizeof(float));
    cudaMemsetAsync(m_h2,  0, (size_t)MROWS * H2 * sizeof(float));
    cudaMemsetAsync(m_out, 0, (size_t)BATCH * NCLS * sizeof(float));

    // pooling for all timesteps
    {
        int total = MALL * INDIM;
        pool_kernel<<<(total + 255) / 256, 256>>>(x);
    }

    // fc1 pre-activations for ALL timesteps in one GEMM: [19968x1024]x[512x1024]^T
    {
        dim3 grid(H0 / 128, MALL / 128);
        sgemm_kernel<128, 128, 16, 8, 8, false><<<grid, 256>>>(
            pooled, W_in, b_in, cur1, nullptr, MALL, H0, INDIM, 0.5f);
    }

    // sequential timestep loop (membrane dependence)
    for (int t = 0; t < TSTEPS; t++) {
        lif_kernel<<<(MROWS * H0 + 255) / 256, 256>>>(
            cur1 + (size_t)t * MROWS * H0, m_in, s1, MROWS * H0, 0.5f);

        dim3 g2(H1 / 64, MROWS / 64);
        sgemm_kernel<64, 64, 16, 4, 4, true><<<g2, 256>>>(
            s1, W_h1, b_h1, s2, m_h1, MROWS, H1, H0, 0.5f);

        dim3 g3(H2 / 64, MROWS / 64);
        sgemm_kernel<64, 64, 16, 4, 4, true><<<g3, 256>>>(
            s2, W_h2, b_h2, s3, m_h2, MROWS, H2, H1, 0.5f);

        fcout_kernel<<<BATCH, 256>>>(s3, W_out, b_out, m_out,
                                     out + (size_t)t * BATCH * NCLS);
    }
}

// round 2
// speedup vs baseline: 1.0303x; 1.0303x over previous
#include <cuda_runtime.h>
#include <cuda_bf16.h>
#include <cstdint>
#include <cstddef>

typedef __nv_bfloat16 bf16;

// ---------------- problem constants ----------------
#define TSTEPS 8
#define BATCH  64
#define CC     3
#define NWIN   232
#define HH     64
#define WW     64
#define CHUNK  29
#define DPP    13
#define INDIM  1024
#define H0     512
#define H1     512
#define H2     256
#define CD     39
#define FEAT   9984
#define NCLS   4
#define MROWS  (BATCH*CD)        // 2496
#define MALL   (TSTEPS*MROWS)    // 19968
#define BETA   0.9f

// ---------------- scratch (static device memory) ----------------
__device__ bf16  g_Ah[(size_t)MALL * INDIM];
__device__ bf16  g_Am[(size_t)MALL * INDIM];
__device__ bf16  g_Al[(size_t)MALL * INDIM];
__device__ float g_cur1[(size_t)MALL * H0];
__device__ bf16  g_s1[(size_t)MROWS * H0];
__device__ bf16  g_s2[(size_t)MROWS * H1];
__device__ bf16  g_s3[(size_t)MROWS * H2];
__device__ float g_min [(size_t)MROWS * H0];
__device__ float g_mh1 [(size_t)MROWS * H1];
__device__ float g_mh2 [(size_t)MROWS * H2];
__device__ float g_mout[(size_t)BATCH * NCLS];
// weight splits
__device__ bf16 g_Wih[H0 * INDIM], g_Wim[H0 * INDIM], g_Wil[H0 * INDIM];
__device__ bf16 g_W1h[H1 * H0],    g_W1m[H1 * H0],    g_W1l[H1 * H0];
__device__ bf16 g_W2h[H2 * H1],    g_W2m[H2 * H1],    g_W2l[H2 * H1];

// ---------------- exact fp32 -> 3x bf16 split ----------------
__device__ __forceinline__ void split3(float a, bf16& h, bf16& m, bf16& l) {
    h = __float2bfloat16(a);
    float r = a - __bfloat162float(h);     // exact (Sterbenz)
    m = __float2bfloat16(r);
    float r2 = r - __bfloat162float(m);    // exact
    l = __float2bfloat16(r2);              // exact (<=8 remaining bits)
}

__global__ void wsplit_kernel(const float* __restrict__ w, int n,
                              bf16* __restrict__ h, bf16* __restrict__ m,
                              bf16* __restrict__ l) {
    int i = blockIdx.x * blockDim.x + threadIdx.x;
    if (i >= n) return;
    bf16 a, b, c;
    split3(w[i], a, b, c);
    h[i] = a; m[i] = b; l[i] = c;
}

// ---------------- avg-pool3d fused with A-matrix 3-split ----------------
__global__ void pool_kernel(const float* __restrict__ x) {
    int idx = blockIdx.x * blockDim.x + threadIdx.x;
    if (idx >= MALL * INDIM) return;
    int hw = idx & (INDIM - 1);
    int r  = idx >> 10;
    int cd = r % CD;
    int tb = r / CD;
    int b  = tb % BATCH;
    int t  = tb / BATCH;
    int c  = cd / DPP;
    int dp = cd % DPP;
    int hp = hw >> 5;
    int wp = hw & 31;
    int d0 = t * CHUNK + 2 * dp;
    const float* base = x + (((size_t)b * CC + c) * NWIN) * (HH * WW)
                          + (size_t)(2 * hp) * WW + (size_t)(2 * wp);
    float s = 0.f;
#pragma unroll
    for (int kd = 0; kd < 4; kd++) {
        const float* p = base + (size_t)(d0 + kd) * (HH * WW);
        float2 r0 = *(const float2*)(p);
        float2 r1 = *(const float2*)(p + WW);
        s += (r0.x + r0.y) + (r1.x + r1.y);
    }
    s *= (1.0f / 16.0f);
    bf16 hb, mb, lb;
    split3(s, hb, mb, lb);
    g_Ah[idx] = hb; g_Am[idx] = mb; g_Al[idx] = lb;
}

// ---------------- bf16 tensor-core multi-term GEMM ----------------
struct Terms {
    const bf16* A[6];
    const bf16* B[6];
};

__device__ __forceinline__ void mma16816(float* c, const uint32_t* a, const uint32_t* b) {
    asm volatile(
        "mma.sync.aligned.m16n8k16.row.col.f32.bf16.bf16.f32 "
        "{%0,%1,%2,%3},{%4,%5,%6,%7},{%8,%9},{%0,%1,%2,%3};\n"
        : "+f"(c[0]), "+f"(c[1]), "+f"(c[2]), "+f"(c[3])
        : "r"(a[0]), "r"(a[1]), "r"(a[2]), "r"(a[3]), "r"(b[0]), "r"(b[1]));
}

// C = sum_t A_t * B_t^T (+bias) [+ fused LIF].  A_t: MxK row-major bf16,
// B_t: NxK row-major bf16 (consumed as col-major k x n by mma).
template<int BM, int BN, int BK, int WM, int WN, int NT, bool LIF>
__global__ void __launch_bounds__((BM/WM)*(BN/WN)*32, 2)
mma_gemm(Terms terms, const float* __restrict__ bias,
         float* __restrict__ curOut, bf16* __restrict__ spkOut,
         float* __restrict__ mem, int M, int N, int K, float thr) {
    constexpr int NWARP   = (BM/WM)*(BN/WN);
    constexpr int THREADS = NWARP * 32;
    constexpr int PAD     = 8;
    constexpr int MF = WM / 16, NF = WN / 8;
    static_assert((BM*BK/8) % THREADS == 0 && (BN*BK/8) % THREADS == 0, "tile load");

    __shared__ bf16 As[BM][BK + PAD];
    __shared__ bf16 Bs[BN][BK + PAD];

    const int tid  = threadIdx.x;
    const int lane = tid & 31;
    const int warp = tid >> 5;
    const int g    = lane >> 2;
    const int tg   = lane & 3;
    const int wn0  = (warp % (BN/WN)) * WN;
    const int wm0  = (warp / (BN/WN)) * WM;
    const int bm   = blockIdx.y * BM;
    const int bn   = blockIdx.x * BN;

    float acc[MF][NF][4];
#pragma unroll
    for (int i = 0; i < MF; i++)
#pragma unroll
        for (int j = 0; j < NF; j++)
#pragma unroll
            for (int q = 0; q < 4; q++) acc[i][j][q] = 0.f;

    for (int t = 0; t < NT; t++) {
        const bf16* __restrict__ Ag = terms.A[t];
        const bf16* __restrict__ Bg = terms.B[t];
        for (int k0 = 0; k0 < K; k0 += BK) {
            constexpr int AIT = (BM*BK/8) / THREADS;
#pragma unroll
            for (int it = 0; it < AIT; it++) {
                int idx = tid + it * THREADS;
                int r = idx / (BK/8);
                int c = (idx % (BK/8)) * 8;
                *(uint4*)&As[r][c] = *(const uint4*)(Ag + (size_t)(bm + r) * K + k0 + c);
            }
            constexpr int BIT = (BN*BK/8) / THREADS;
#pragma unroll
            for (int it = 0; it < BIT; it++) {
                int idx = tid + it * THREADS;
                int r = idx / (BK/8);
                int c = (idx % (BK/8)) * 8;
                *(uint4*)&Bs[r][c] = *(const uint4*)(Bg + (size_t)(bn + r) * K + k0 + c);
            }
            __syncthreads();
#pragma unroll
            for (int ks = 0; ks < BK; ks += 16) {
                uint32_t fa[MF][4], fb[NF][2];
#pragma unroll
                for (int mf = 0; mf < MF; mf++) {
                    const bf16* ap = &As[wm0 + mf*16 + g][ks + 2*tg];
                    fa[mf][0] = *(const uint32_t*)ap;
                    fa[mf][1] = *(const uint32_t*)(ap + 8*(BK+PAD));
                    fa[mf][2] = *(const uint32_t*)(ap + 8);
                    fa[mf][3] = *(const uint32_t*)(ap + 8*(BK+PAD) + 8);
                }
#pragma unroll
                for (int nf = 0; nf < NF; nf++) {
                    const bf16* bp = &Bs[wn0 + nf*8 + g][ks + 2*tg];
                    fb[nf][0] = *(const uint32_t*)bp;
                    fb[nf][1] = *(const uint32_t*)(bp + 8);
                }
#pragma unroll
                for (int mf = 0; mf < MF; mf++)
#pragma unroll
                    for (int nf = 0; nf < NF; nf++)
                        mma16816(acc[mf][nf], fa[mf], fb[nf]);
            }
            __syncthreads();
        }
    }

    // epilogue
#pragma unroll
    for (int mf = 0; mf < MF; mf++) {
#pragma unroll
        for (int nf = 0; nf < NF; nf++) {
            int m0 = bm + wm0 + mf*16 + g;
            int n0 = bn + wn0 + nf*8 + 2*tg;
#pragma unroll
            for (int q = 0; q < 4; q++) {
                int m = m0 + (q >> 1) * 8;
                int n = n0 + (q & 1);
                size_t o = (size_t)m * N + n;
                float v = acc[mf][nf][q] + bias[n];
                if (LIF) {
                    float mo = mem[o];
                    float mn = BETA * mo + v - (mo > thr ? thr : 0.f);
                    mem[o] = mn;
                    spkOut[o] = __float2bfloat16((mn - thr) > 0.f ? 1.f : 0.f);
                } else {
                    curOut[o] = v;
                }
            }
        }
    }
}

// ---------------- elementwise LIF for layer 1 ----------------
__global__ void lif_kernel(const float* __restrict__ cur,
                           float* __restrict__ mem,
                           bf16* __restrict__ spk, int n, float thr) {
    int i = blockIdx.x * blockDim.x + threadIdx.x;
    if (i >= n) return;
    float mo = mem[i];
    float mn = BETA * mo + cur[i] - (mo > thr ? thr : 0.f);
    mem[i] = mn;
    spk[i] = __float2bfloat16((mn - thr) > 0.f ? 1.f : 0.f);
}

// ---------------- readout: 64 x (9984 -> 4) + LIF(thr=1) ----------------
__global__ void fcout_kernel(const bf16* __restrict__ s3,
                             const float* __restrict__ Wout,
                             const float* __restrict__ bout,
                             float* __restrict__ mout,
                             float* __restrict__ out_t) {
    const int b   = blockIdx.x;
    const int tid = threadIdx.x;   // 256
    const bf16* sp = s3 + (size_t)b * FEAT;
    float a0 = 0.f, a1 = 0.f, a2 = 0.f, a3 = 0.f;
    for (int k = tid; k < FEAT; k += 256) {
        if (__bfloat162float(sp[k]) != 0.f) {
            a0 += Wout[0 * FEAT + k];
            a1 += Wout[1 * FEAT + k];
            a2 += Wout[2 * FEAT + k];
            a3 += Wout[3 * FEAT + k];
        }
    }
    __shared__ float red[4][256];
    red[0][tid] = a0; red[1][tid] = a1; red[2][tid] = a2; red[3][tid] = a3;
    __syncthreads();
    for (int st = 128; st > 0; st >>= 1) {
        if (tid < st) {
#pragma unroll
            for (int n = 0; n < 4; n++) red[n][tid] += red[n][tid + st];
        }
        __syncthreads();
    }
    if (tid < NCLS) {
        float cur = red[tid][0] + bout[tid];
        float mo  = mout[b * NCLS + tid];
        float mn  = BETA * mo + cur - (mo > 1.0f ? 1.0f : 0.f);
        mout[b * NCLS + tid] = mn;
        out_t[b * NCLS + tid] = (mn - 1.0f) > 0.f ? 1.f : 0.f;
    }
}

// ---------------- host orchestration (graph-capturable) ----------------
extern "C" void kernel_launch(void* const* d_in, const int* in_sizes, int n_in,
                              void* d_out, int out_size) {
    const float* x     = (const float*)d_in[0];
    const float* W_in  = (const float*)d_in[1];
    const float* b_in  = (const float*)d_in[2];
    const float* W_h1  = (const float*)d_in[3];
    const float* b_h1  = (const float*)d_in[4];
    const float* W_h2  = (const float*)d_in[5];
    const float* b_h2  = (const float*)d_in[6];
    const float* W_out = (const float*)d_in[7];
    const float* b_out = (const float*)d_in[8];
    float* out = (float*)d_out;

    bf16 *Ah, *Am, *Al, *s1, *s2, *s3;
    bf16 *Wih, *Wim, *Wil, *W1h, *W1m, *W1l, *W2h, *W2m, *W2l;
    float *cur1, *m_in, *m_h1, *m_h2, *m_out;
    cudaGetSymbolAddress((void**)&Ah, g_Ah);
    cudaGetSymbolAddress((void**)&Am, g_Am);
    cudaGetSymbolAddress((void**)&Al, g_Al);
    cudaGetSymbolAddress((void**)&cur1, g_cur1);
    cudaGetSymbolAddress((void**)&s1, g_s1);
    cudaGetSymbolAddress((void**)&s2, g_s2);
    cudaGetSymbolAddress((void**)&s3, g_s3);
    cudaGetSymbolAddress((void**)&m_in, g_min);
    cudaGetSymbolAddress((void**)&m_h1, g_mh1);
    cudaGetSymbolAddress((void**)&m_h2, g_mh2);
    cudaGetSymbolAddress((void**)&m_out, g_mout);
    cudaGetSymbolAddress((void**)&Wih, g_Wih);
    cudaGetSymbolAddress((void**)&Wim, g_Wim);
    cudaGetSymbolAddress((void**)&Wil, g_Wil);
    cudaGetSymbolAddress((void**)&W1h, g_W1h);
    cudaGetSymbolAddress((void**)&W1m, g_W1m);
    cudaGetSymbolAddress((void**)&W1l, g_W1l);
    cudaGetSymbolAddress((void**)&W2h, g_W2h);
    cudaGetSymbolAddress((void**)&W2m, g_W2m);
    cudaGetSymbolAddress((void**)&W2l, g_W2l);

    // zero membrane state (deterministic per call)
    cudaMemsetAsync(m_in,  0, (size_t)MROWS * H0 * sizeof(float));
    cudaMemsetAsync(m_h1,  0, (size_t)MROWS * H1 * sizeof(float));
    cudaMemsetAsync(m_h2,  0, (size_t)MROWS * H2 * sizeof(float));
    cudaMemsetAsync(m_out, 0, (size_t)BATCH * NCLS * sizeof(float));

    // weight splits (cheap, every call)
    wsplit_kernel<<<(H0*INDIM + 255)/256, 256>>>(W_in, H0*INDIM, Wih, Wim, Wil);
    wsplit_kernel<<<(H1*H0   + 255)/256, 256>>>(W_h1, H1*H0,   W1h, W1m, W1l);
    wsplit_kernel<<<(H2*H1   + 255)/256, 256>>>(W_h2, H2*H1,   W2h, W2m, W2l);

    // pool + A split for all timesteps
    pool_kernel<<<(MALL*INDIM + 255)/256, 256>>>(x);

    // fc1 for ALL timesteps, 6-term exact bf16 split GEMM (K-levels 0..2)
    {
        Terms t1;
        t1.A[0]=Ah;  t1.B[0]=Wih;
        t1.A[1]=Ah;  t1.B[1]=Wim;
        t1.A[2]=Am;  t1.B[2]=Wih;
        t1.A[3]=Ah;  t1.B[3]=Wil;
        t1.A[4]=Am;  t1.B[4]=Wim;
        t1.A[5]=Al;  t1.B[5]=Wih;
        dim3 grid(H0/128, MALL/128);
        mma_gemm<128,128,32,64,32,6,false><<<grid, 256>>>(
            t1, b_in, cur1, nullptr, nullptr, MALL, H0, INDIM, 0.f);
    }

    // sequential timestep loop
    for (int t = 0; t < TSTEPS; t++) {
        lif_kernel<<<(MROWS*H0 + 255)/256, 256>>>(
            cur1 + (size_t)t * MROWS * H0, m_in, s1, MROWS*H0, 0.5f);

        Terms t2;
        t2.A[0]=s1; t2.B[0]=W1h;
        t2.A[1]=s1; t2.B[1]=W1m;
        t2.A[2]=s1; t2.B[2]=W1l;
        t2.A[3]=t2.A[4]=t2.A[5]=s1; t2.B[3]=t2.B[4]=t2.B[5]=W1h;
        mma_gemm<64,128,32,32,32,3,true><<<dim3(H1/128, MROWS/64), 256>>>(
            t2, b_h1, nullptr, s2, m_h1, MROWS, H1, H0, 0.5f);

        Terms t3;
        t3.A[0]=s2; t3.B[0]=W2h;
        t3.A[1]=s2; t3.B[1]=W2m;
        t3.A[2]=s2; t3.B[2]=W2l;
        t3.A[3]=t3.A[4]=t3.A[5]=s2; t3.B[3]=t3.B[4]=t3.B[5]=W2h;
        mma_gemm<64,128,32,32,32,3,true><<<dim3(H2/128, MROWS/64), 256>>>(
            t3, b_h2, nullptr, s3, m_h2, MROWS, H2, H1, 0.5f);

        fcout_kernel<<<BATCH, 256>>>(s3, W_out, b_out, m_out,
                                     out + (size_t)t * BATCH * NCLS);
    }
}

// round 3
// speedup vs baseline: 1.3800x; 1.3395x over previous
#include <cuda_runtime.h>
#include <cuda_bf16.h>
#include <cstdint>
#include <cstddef>

typedef __nv_bfloat16 bf16;

// ---------------- problem constants ----------------
#define TSTEPS 8
#define BATCH  64
#define CC     3
#define NWIN   232
#define HH     64
#define WW     64
#define CHUNK  29
#define DPP    13
#define INDIM  1024
#define H0     512
#define H1     512
#define H2     256
#define CD     39
#define FEAT   9984
#define NCLS   4
#define MROWS  (BATCH*CD)        // 2496
#define MALL   (TSTEPS*MROWS)    // 19968
#define BETA   0.9f

// ---------------- scratch (static device memory) ----------------
__device__ bf16  g_Ah[(size_t)MALL * INDIM];
__device__ bf16  g_Am[(size_t)MALL * INDIM];
__device__ bf16  g_Al[(size_t)MALL * INDIM];
__device__ float g_cur1[(size_t)MALL * H0];
__device__ bf16  g_s1[(size_t)MROWS * H0];
__device__ bf16  g_s2[(size_t)MROWS * H1];
__device__ bf16  g_s3[(size_t)MROWS * H2];
__device__ float g_min [(size_t)MROWS * H0];
__device__ float g_mh1 [(size_t)MROWS * H1];
__device__ float g_mh2 [(size_t)MROWS * H2];
__device__ float g_mout[(size_t)BATCH * NCLS];
__device__ bf16 g_Wih[H0 * INDIM], g_Wim[H0 * INDIM], g_Wil[H0 * INDIM];
__device__ bf16 g_W1h[H1 * H0],    g_W1m[H1 * H0],    g_W1l[H1 * H0];
__device__ bf16 g_W2h[H2 * H1],    g_W2m[H2 * H1],    g_W2l[H2 * H1];

// ---------------- exact fp32 -> 3x bf16 split ----------------
__device__ __forceinline__ void split3(float a, bf16& h, bf16& m, bf16& l) {
    h = __float2bfloat16(a);
    float r = a - __bfloat162float(h);     // exact
    m = __float2bfloat16(r);
    float r2 = r - __bfloat162float(m);    // exact
    l = __float2bfloat16(r2);
}

__global__ void wsplit_kernel(const float* __restrict__ w, int n,
                              bf16* __restrict__ h, bf16* __restrict__ m,
                              bf16* __restrict__ l) {
    int i = blockIdx.x * blockDim.x + threadIdx.x;
    if (i >= n) return;
    bf16 a, b, c;
    split3(w[i], a, b, c);
    h[i] = a; m[i] = b; l[i] = c;
}

// ---------------- avg-pool3d fused with A-matrix 3-split ----------------
__global__ void pool_kernel(const float* __restrict__ x) {
    int idx = blockIdx.x * blockDim.x + threadIdx.x;
    if (idx >= MALL * INDIM) return;
    int hw = idx & (INDIM - 1);
    int r  = idx >> 10;
    int cd = r % CD;
    int tb = r / CD;
    int b  = tb % BATCH;
    int t  = tb / BATCH;
    int c  = cd / DPP;
    int dp = cd % DPP;
    int hp = hw >> 5;
    int wp = hw & 31;
    int d0 = t * CHUNK + 2 * dp;
    const float* base = x + (((size_t)b * CC + c) * NWIN) * (HH * WW)
                          + (size_t)(2 * hp) * WW + (size_t)(2 * wp);
    float s = 0.f;
#pragma unroll
    for (int kd = 0; kd < 4; kd++) {
        const float* p = base + (size_t)(d0 + kd) * (HH * WW);
        float2 r0 = *(const float2*)(p);
        float2 r1 = *(const float2*)(p + WW);
        s += (r0.x + r0.y) + (r1.x + r1.y);
    }
    s *= (1.0f / 16.0f);
    bf16 hb, mb, lb;
    split3(s, hb, mb, lb);
    g_Ah[idx] = hb; g_Am[idx] = mb; g_Al[idx] = lb;
}

// ---------------- cp.async helpers ----------------
__device__ __forceinline__ void cpasync16(void* s, const void* g) {
    uint32_t sa = (uint32_t)__cvta_generic_to_shared(s);
    asm volatile("cp.async.cg.shared.global [%0], [%1], 16;\n" :: "r"(sa), "l"(g));
}
__device__ __forceinline__ void cp_commit() {
    asm volatile("cp.async.commit_group;\n");
}
template<int N> __device__ __forceinline__ void cp_wait() {
    asm volatile("cp.async.wait_group %0;\n" :: "n"(N));
}

// ---------------- bf16 tensor-core multi-term GEMM, 3-stage pipeline ------
struct Terms {
    const bf16* A[6];
    const bf16* B[6];
};

__device__ __forceinline__ void mma16816(float* c, const uint32_t* a, const uint32_t* b) {
    asm volatile(
        "mma.sync.aligned.m16n8k16.row.col.f32.bf16.bf16.f32 "
        "{%0,%1,%2,%3},{%4,%5,%6,%7},{%8,%9},{%0,%1,%2,%3};\n"
        : "+f"(c[0]), "+f"(c[1]), "+f"(c[2]), "+f"(c[3])
        : "r"(a[0]), "r"(a[1]), "r"(a[2]), "r"(a[3]), "r"(b[0]), "r"(b[1]));
}

template<int BM, int BN, int BK, int WM, int WN, int NT, int K, bool LIF>
__global__ void __launch_bounds__((BM/WM)*(BN/WN)*32, 2)
mma_gemm(Terms terms, const float* __restrict__ bias,
         float* __restrict__ curOut, bf16* __restrict__ spkOut,
         float* __restrict__ mem, int M, int N, float thr) {
    constexpr int NWARP   = (BM/WM)*(BN/WN);
    constexpr int THREADS = NWARP * 32;
    constexpr int PAD     = 8;
    constexpr int LDW     = BK + PAD;
    constexpr int STAGES  = 3;
    constexpr int KT      = K / BK;        // k-tiles per term
    constexpr int NTILE   = NT * KT;
    constexpr int MF = WM / 16, NF = WN / 8;
    constexpr int AIT = (BM * BK / 8) / THREADS;
    constexpr int BIT = (BN * BK / 8) / THREADS;
    static_assert(AIT >= 1 && BIT >= 1, "tile load");

    extern __shared__ char dynsmem[];
    bf16 (*As)[BM][LDW] = (bf16(*)[BM][LDW])dynsmem;
    bf16 (*Bs)[BN][LDW] = (bf16(*)[BN][LDW])(dynsmem + (size_t)STAGES * BM * LDW * 2);

    const int tid  = threadIdx.x;
    const int lane = tid & 31;
    const int warp = tid >> 5;
    const int g    = lane >> 2;
    const int tg   = lane & 3;
    const int wn0  = (warp % (BN/WN)) * WN;
    const int wm0  = (warp / (BN/WN)) * WM;
    const int bm   = blockIdx.y * BM;
    const int bn   = blockIdx.x * BN;

    const int lr = tid / (BK/8);           // loader row within tile pass
    const int lc = (tid % (BK/8)) * 8;     // loader col (elements)
    constexpr int AROWS = THREADS / (BK/8);

    auto load_tile = [&](int i, int s) {
        const int term = i / KT;
        const int k0   = (i % KT) * BK;
        const bf16* __restrict__ Ag = terms.A[term] + (size_t)bm * K + k0;
        const bf16* __restrict__ Bg = terms.B[term] + (size_t)bn * K + k0;
#pragma unroll
        for (int it = 0; it < AIT; it++)
            cpasync16(&As[s][lr + it*AROWS][lc], Ag + (size_t)(lr + it*AROWS) * K + lc);
#pragma unroll
        for (int it = 0; it < BIT; it++)
            cpasync16(&Bs[s][lr + it*AROWS][lc], Bg + (size_t)(lr + it*AROWS) * K + lc);
        cp_commit();
    };

    float acc[MF][NF][4];
#pragma unroll
    for (int i = 0; i < MF; i++)
#pragma unroll
        for (int j = 0; j < NF; j++)
#pragma unroll
            for (int q = 0; q < 4; q++) acc[i][j][q] = 0.f;

    // prologue: stages 0..STAGES-2
#pragma unroll
    for (int i = 0; i < STAGES - 1; i++) load_tile(i, i);

    for (int i = 0; i < NTILE; i++) {
        cp_wait<STAGES - 2>();
        __syncthreads();
        const int nxt = i + STAGES - 1;
        if (nxt < NTILE) load_tile(nxt, nxt % STAGES);
        const int st = i % STAGES;
#pragma unroll
        for (int ks = 0; ks < BK; ks += 16) {
            uint32_t fa[MF][4], fb[NF][2];
#pragma unroll
            for (int mf = 0; mf < MF; mf++) {
                const bf16* ap = &As[st][wm0 + mf*16 + g][ks + 2*tg];
                fa[mf][0] = *(const uint32_t*)ap;
                fa[mf][1] = *(const uint32_t*)(ap + 8*LDW);
                fa[mf][2] = *(const uint32_t*)(ap + 8);
                fa[mf][3] = *(const uint32_t*)(ap + 8*LDW + 8);
            }
#pragma unroll
            for (int nf = 0; nf < NF; nf++) {
                const bf16* bp = &Bs[st][wn0 + nf*8 + g][ks + 2*tg];
                fb[nf][0] = *(const uint32_t*)bp;
                fb[nf][1] = *(const uint32_t*)(bp + 8);
            }
#pragma unroll
            for (int mf = 0; mf < MF; mf++)
#pragma unroll
                for (int nf = 0; nf < NF; nf++)
                    mma16816(acc[mf][nf], fa[mf], fb[nf]);
        }
    }

    // epilogue
#pragma unroll
    for (int mf = 0; mf < MF; mf++) {
#pragma unroll
        for (int nf = 0; nf < NF; nf++) {
            int m0 = bm + wm0 + mf*16 + g;
            int n0 = bn + wn0 + nf*8 + 2*tg;
#pragma unroll
            for (int q = 0; q < 4; q++) {
                int m = m0 + (q >> 1) * 8;
                int n = n0 + (q & 1);
                size_t o = (size_t)m * N + n;
                float v = acc[mf][nf][q] + bias[n];
                if (LIF) {
                    float mo = mem[o];
                    float mn = BETA * mo + v - (mo > thr ? thr : 0.f);
                    mem[o] = mn;
                    spkOut[o] = __float2bfloat16((mn - thr) > 0.f ? 1.f : 0.f);
                } else {
                    curOut[o] = v;
                }
            }
        }
    }
}

// ---------------- elementwise LIF for layer 1 ----------------
__global__ void lif_kernel(const float* __restrict__ cur,
                           float* __restrict__ mem,
                           bf16* __restrict__ spk, int n, float thr) {
    int i = blockIdx.x * blockDim.x + threadIdx.x;
    if (i >= n) return;
    float mo = mem[i];
    float mn = BETA * mo + cur[i] - (mo > thr ? thr : 0.f);
    mem[i] = mn;
    spk[i] = __float2bfloat16((mn - thr) > 0.f ? 1.f : 0.f);
}

// ---------------- readout ----------------
__global__ void fcout_kernel(const bf16* __restrict__ s3,
                             const float* __restrict__ Wout,
                             const float* __restrict__ bout,
                             float* __restrict__ mout,
                             float* __restrict__ out_t) {
    const int b   = blockIdx.x;
    const int tid = threadIdx.x;   // 256
    const bf16* sp = s3 + (size_t)b * FEAT;
    float a0 = 0.f, a1 = 0.f, a2 = 0.f, a3 = 0.f;
    for (int k = tid; k < FEAT; k += 256) {
        if (__bfloat162float(sp[k]) != 0.f) {
            a0 += Wout[0 * FEAT + k];
            a1 += Wout[1 * FEAT + k];
            a2 += Wout[2 * FEAT + k];
            a3 += Wout[3 * FEAT + k];
        }
    }
    __shared__ float red[4][256];
    red[0][tid] = a0; red[1][tid] = a1; red[2][tid] = a2; red[3][tid] = a3;
    __syncthreads();
    for (int st = 128; st > 0; st >>= 1) {
        if (tid < st) {
#pragma unroll
            for (int n = 0; n < 4; n++) red[n][tid] += red[n][tid + st];
        }
        __syncthreads();
    }
    if (tid < NCLS) {
        float cur = red[tid][0] + bout[tid];
        float mo  = mout[b * NCLS + tid];
        float mn  = BETA * mo + cur - (mo > 1.0f ? 1.0f : 0.f);
        mout[b * NCLS + tid] = mn;
        out_t[b * NCLS + tid] = (mn - 1.0f) > 0.f ? 1.f : 0.f;
    }
}

// ---------------- host orchestration ----------------
extern "C" void kernel_launch(void* const* d_in, const int* in_sizes, int n_in,
                              void* d_out, int out_size) {
    const float* x     = (const float*)d_in[0];
    const float* W_in  = (const float*)d_in[1];
    const float* b_in  = (const float*)d_in[2];
    const float* W_h1  = (const float*)d_in[3];
    const float* b_h1  = (const float*)d_in[4];
    const float* W_h2  = (const float*)d_in[5];
    const float* b_h2  = (const float*)d_in[6];
    const float* W_out = (const float*)d_in[7];
    const float* b_out = (const float*)d_in[8];
    float* out = (float*)d_out;

    bf16 *Ah, *Am, *Al, *s1, *s2, *s3;
    bf16 *Wih, *Wim, *Wil, *W1h, *W1m, *W1l, *W2h, *W2m, *W2l;
    float *cur1, *m_in, *m_h1, *m_h2, *m_out;
    cudaGetSymbolAddress((void**)&Ah, g_Ah);
    cudaGetSymbolAddress((void**)&Am, g_Am);
    cudaGetSymbolAddress((void**)&Al, g_Al);
    cudaGetSymbolAddress((void**)&cur1, g_cur1);
    cudaGetSymbolAddress((void**)&s1, g_s1);
    cudaGetSymbolAddress((void**)&s2, g_s2);
    cudaGetSymbolAddress((void**)&s3, g_s3);
    cudaGetSymbolAddress((void**)&m_in, g_min);
    cudaGetSymbolAddress((void**)&m_h1, g_mh1);
    cudaGetSymbolAddress((void**)&m_h2, g_mh2);
    cudaGetSymbolAddress((void**)&m_out, g_mout);
    cudaGetSymbolAddress((void**)&Wih, g_Wih);
    cudaGetSymbolAddress((void**)&Wim, g_Wim);
    cudaGetSymbolAddress((void**)&Wil, g_Wil);
    cudaGetSymbolAddress((void**)&W1h, g_W1h);
    cudaGetSymbolAddress((void**)&W1m, g_W1m);
    cudaGetSymbolAddress((void**)&W1l, g_W1l);
    cudaGetSymbolAddress((void**)&W2h, g_W2h);
    cudaGetSymbolAddress((void**)&W2m, g_W2m);
    cudaGetSymbolAddress((void**)&W2l, g_W2l);

    // smem sizes
    constexpr int SMEM_FC1 = 3 * (128 * 72 + 128 * 72) * 2;   // 110592
    constexpr int SMEM_FC2 = 3 * (64 * 72 + 64 * 72) * 2;     // 55296
    auto kfc1 = mma_gemm<128,128,64,64,32,6,1024,false>;
    auto kfc2 = mma_gemm<64,64,64,32,32,3,512,true>;
    cudaFuncSetAttribute(kfc1, cudaFuncAttributeMaxDynamicSharedMemorySize, SMEM_FC1);
    cudaFuncSetAttribute(kfc2, cudaFuncAttributeMaxDynamicSharedMemorySize, SMEM_FC2);

    cudaMemsetAsync(m_in,  0, (size_t)MROWS * H0 * sizeof(float));
    cudaMemsetAsync(m_h1,  0, (size_t)MROWS * H1 * sizeof(float));
    cudaMemsetAsync(m_h2,  0, (size_t)MROWS * H2 * sizeof(float));
    cudaMemsetAsync(m_out, 0, (size_t)BATCH * NCLS * sizeof(float));

    wsplit_kernel<<<(H0*INDIM + 255)/256, 256>>>(W_in, H0*INDIM, Wih, Wim, Wil);
    wsplit_kernel<<<(H1*H0   + 255)/256, 256>>>(W_h1, H1*H0,   W1h, W1m, W1l);
    wsplit_kernel<<<(H2*H1   + 255)/256, 256>>>(W_h2, H2*H1,   W2h, W2m, W2l);

    pool_kernel<<<(MALL*INDIM + 255)/256, 256>>>(x);

    // fc1 all timesteps: 6-term exact bf16 split GEMM
    {
        Terms t1;
        t1.A[0]=Ah;  t1.B[0]=Wih;
        t1.A[1]=Ah;  t1.B[1]=Wim;
        t1.A[2]=Am;  t1.B[2]=Wih;
        t1.A[3]=Ah;  t1.B[3]=Wil;
        t1.A[4]=Am;  t1.B[4]=Wim;
        t1.A[5]=Al;  t1.B[5]=Wih;
        dim3 grid(H0/128, MALL/128);
        kfc1<<<grid, 256, SMEM_FC1>>>(t1, b_in, cur1, nullptr, nullptr,
                                      MALL, H0, 0.f);
    }

    for (int t = 0; t < TSTEPS; t++) {
        lif_kernel<<<(MROWS*H0 + 255)/256, 256>>>(
            cur1 + (size_t)t * MROWS * H0, m_in, s1, MROWS*H0, 0.5f);

        Terms t2;
        t2.A[0]=s1; t2.B[0]=W1h;
        t2.A[1]=s1; t2.B[1]=W1m;
        t2.A[2]=s1; t2.B[2]=W1l;
        t2.A[3]=t2.A[4]=t2.A[5]=s1; t2.B[3]=t2.B[4]=t2.B[5]=W1h;
        kfc2<<<dim3(H1/64, MROWS/64), 128, SMEM_FC2>>>(
            t2, b_h1, nullptr, s2, m_h1, MROWS, H1, 0.5f);

        Terms t3;
        t3.A[0]=s2; t3.B[0]=W2h;
        t3.A[1]=s2; t3.B[1]=W2m;
        t3.A[2]=s2; t3.B[2]=W2l;
        t3.A[3]=t3.A[4]=t3.A[5]=s2; t3.B[3]=t3.B[4]=t3.B[5]=W2h;
        kfc2<<<dim3(H2/64, MROWS/64), 128, SMEM_FC2>>>(
            t3, b_h2, nullptr, s3, m_h2, MROWS, H2, 0.5f);

        fcout_kernel<<<BATCH, 256>>>(s3, W_out, b_out, m_out,
                                     out + (size_t)t * BATCH * NCLS);
    }
}

// round 4
// speedup vs baseline: 1.4044x; 1.0177x over previous
#include <cuda_runtime.h>
#include <cuda_bf16.h>
#include <cstdint>
#include <cstddef>

typedef __nv_bfloat16 bf16;

// ---------------- problem constants ----------------
#define TSTEPS 8
#define BATCH  64
#define CC     3
#define NWIN   232
#define HH     64
#define WW     64
#define CHUNK  29
#define DPP    13
#define INDIM  1024
#define H0     512
#define H1     512
#define H2     256
#define CD     39
#define FEAT   9984
#define NCLS   4
#define MROWS  (BATCH*CD)        // 2496
#define MALL   (TSTEPS*MROWS)    // 19968
#define BETA   0.9f

// ---------------- scratch (static device memory) ----------------
__device__ bf16  g_Ah[(size_t)MALL * INDIM];
__device__ bf16  g_Am[(size_t)MALL * INDIM];
__device__ bf16  g_Al[(size_t)MALL * INDIM];
__device__ float g_cur1[(size_t)MALL * H0];
__device__ bf16  g_s1[(size_t)MROWS * H0];
__device__ bf16  g_s2[(size_t)MROWS * H1];
__device__ bf16  g_s3[(size_t)MROWS * H2];
__device__ float g_min [(size_t)MROWS * H0];
__device__ float g_mh1 [(size_t)MROWS * H1];
__device__ float g_mh2 [(size_t)MROWS * H2];
__device__ float g_mout[(size_t)BATCH * NCLS];
__device__ bf16 g_Wih[H0 * INDIM], g_Wim[H0 * INDIM], g_Wil[H0 * INDIM];
__device__ bf16 g_W1h[H1 * H0],    g_W1m[H1 * H0],    g_W1l[H1 * H0];
__device__ bf16 g_W2h[H2 * H1],    g_W2m[H2 * H1],    g_W2l[H2 * H1];

// ---------------- exact fp32 -> 3x bf16 split ----------------
__device__ __forceinline__ void split3(float a, bf16& h, bf16& m, bf16& l) {
    h = __float2bfloat16(a);
    float r = a - __bfloat162float(h);     // exact
    m = __float2bfloat16(r);
    float r2 = r - __bfloat162float(m);    // exact
    l = __float2bfloat16(r2);
}

__global__ void wsplit_kernel(const float* __restrict__ w, int n,
                              bf16* __restrict__ h, bf16* __restrict__ m,
                              bf16* __restrict__ l) {
    int i = blockIdx.x * blockDim.x + threadIdx.x;
    if (i >= n) return;
    bf16 a, b, c;
    split3(w[i], a, b, c);
    h[i] = a; m[i] = b; l[i] = c;
}

// ---------------- avg-pool3d fused with A-matrix 3-split ----------------
__global__ void pool_kernel(const float* __restrict__ x) {
    int idx = blockIdx.x * blockDim.x + threadIdx.x;
    if (idx >= MALL * INDIM) return;
    int hw = idx & (INDIM - 1);
    int r  = idx >> 10;
    int cd = r % CD;
    int tb = r / CD;
    int b  = tb % BATCH;
    int t  = tb / BATCH;
    int c  = cd / DPP;
    int dp = cd % DPP;
    int hp = hw >> 5;
    int wp = hw & 31;
    int d0 = t * CHUNK + 2 * dp;
    const float* base = x + (((size_t)b * CC + c) * NWIN) * (HH * WW)
                          + (size_t)(2 * hp) * WW + (size_t)(2 * wp);
    float s = 0.f;
#pragma unroll
    for (int kd = 0; kd < 4; kd++) {
        const float* p = base + (size_t)(d0 + kd) * (HH * WW);
        float2 r0 = *(const float2*)(p);
        float2 r1 = *(const float2*)(p + WW);
        s += (r0.x + r0.y) + (r1.x + r1.y);
    }
    s *= (1.0f / 16.0f);
    bf16 hb, mb, lb;
    split3(s, hb, mb, lb);
    g_Ah[idx] = hb; g_Am[idx] = mb; g_Al[idx] = lb;
}

// ---------------- cp.async / ldmatrix helpers ----------------
__device__ __forceinline__ void cpasync16(void* s, const void* g) {
    uint32_t sa = (uint32_t)__cvta_generic_to_shared(s);
    asm volatile("cp.async.cg.shared.global [%0], [%1], 16;\n" :: "r"(sa), "l"(g));
}
__device__ __forceinline__ void cp_commit() {
    asm volatile("cp.async.commit_group;\n");
}
template<int N> __device__ __forceinline__ void cp_wait() {
    asm volatile("cp.async.wait_group %0;\n" :: "n"(N));
}
__device__ __forceinline__ void ldmatrix_x4(uint32_t* r, const void* p) {
    uint32_t a = (uint32_t)__cvta_generic_to_shared(p);
    asm volatile("ldmatrix.sync.aligned.m8n8.x4.shared.b16 {%0,%1,%2,%3}, [%4];\n"
        : "=r"(r[0]), "=r"(r[1]), "=r"(r[2]), "=r"(r[3]) : "r"(a));
}

// ---------------- bf16 tensor-core multi-term GEMM, 3-stage pipeline ------
struct Terms {
    const bf16* A[6];
    const bf16* B[6];
};

__device__ __forceinline__ void mma16816(float* c, const uint32_t* a, const uint32_t* b) {
    asm volatile(
        "mma.sync.aligned.m16n8k16.row.col.f32.bf16.bf16.f32 "
        "{%0,%1,%2,%3},{%4,%5,%6,%7},{%8,%9},{%0,%1,%2,%3};\n"
        : "+f"(c[0]), "+f"(c[1]), "+f"(c[2]), "+f"(c[3])
        : "r"(a[0]), "r"(a[1]), "r"(a[2]), "r"(a[3]), "r"(b[0]), "r"(b[1]));
}

template<int BM, int BN, int BK, int WM, int WN, int NT, int K, bool LIF>
__global__ void __launch_bounds__((BM/WM)*(BN/WN)*32)
mma_gemm(Terms terms, const float* __restrict__ bias,
         float* __restrict__ curOut, bf16* __restrict__ spkOut,
         float* __restrict__ mem, int M, int N, float thr) {
    constexpr int NWARP   = (BM/WM)*(BN/WN);
    constexpr int THREADS = NWARP * 32;
    constexpr int PAD     = 8;
    constexpr int LDW     = BK + PAD;
    constexpr int STAGES  = 3;
    constexpr int KT      = K / BK;
    constexpr int NTILE   = NT * KT;
    constexpr int MF = WM / 16, NF = WN / 8;
    static_assert(NF % 2 == 0, "NF even for paired ldmatrix");
    constexpr int AIT = (BM * BK / 8) / THREADS;
    constexpr int BIT = (BN * BK / 8) / THREADS;
    static_assert(AIT >= 1 && BIT >= 1, "tile load");

    extern __shared__ char dynsmem[];
    bf16 (*As)[BM][LDW] = (bf16(*)[BM][LDW])dynsmem;
    bf16 (*Bs)[BN][LDW] = (bf16(*)[BN][LDW])(dynsmem + (size_t)STAGES * BM * LDW * 2);

    const int tid  = threadIdx.x;
    const int lane = tid & 31;
    const int warp = tid >> 5;
    const int g    = lane >> 2;
    const int tg   = lane & 3;
    const int wn0  = (warp % (BN/WN)) * WN;
    const int wm0  = (warp / (BN/WN)) * WM;
    const int bm   = blockIdx.y * BM;
    const int bn   = blockIdx.x * BN;

    // ldmatrix per-lane addressing components
    const int l8   = lane & 7;
    const int aRow = ((lane >> 3) & 1) * 8 + l8;   // row offset within 16
    const int aCol = (lane >> 4) * 8;              // col offset within 16
    const int bRow = (lane >> 4) * 8 + l8;         // row offset within 16
    const int bCol = ((lane >> 3) & 1) * 8;        // col offset within 16

    const int lr = tid / (BK/8);
    const int lc = (tid % (BK/8)) * 8;
    constexpr int AROWS = THREADS / (BK/8);

    auto load_tile = [&](int i, int s) {
        const int term = i / KT;
        const int k0   = (i % KT) * BK;
        const bf16* __restrict__ Ag = terms.A[term] + (size_t)bm * K + k0;
        const bf16* __restrict__ Bg = terms.B[term] + (size_t)bn * K + k0;
#pragma unroll
        for (int it = 0; it < AIT; it++)
            cpasync16(&As[s][lr + it*AROWS][lc], Ag + (size_t)(lr + it*AROWS) * K + lc);
#pragma unroll
        for (int it = 0; it < BIT; it++)
            cpasync16(&Bs[s][lr + it*AROWS][lc], Bg + (size_t)(lr + it*AROWS) * K + lc);
        cp_commit();
    };

    float acc[MF][NF][4];
#pragma unroll
    for (int i = 0; i < MF; i++)
#pragma unroll
        for (int j = 0; j < NF; j++)
#pragma unroll
            for (int q = 0; q < 4; q++) acc[i][j][q] = 0.f;

#pragma unroll
    for (int i = 0; i < STAGES - 1; i++) load_tile(i, i);

    for (int i = 0; i < NTILE; i++) {
        cp_wait<STAGES - 2>();
        __syncthreads();
        const int nxt = i + STAGES - 1;
        if (nxt < NTILE) load_tile(nxt, nxt % STAGES);
        const int st = i % STAGES;
#pragma unroll
        for (int ks = 0; ks < BK; ks += 16) {
            uint32_t fa[MF][4], fb[NF][2];
#pragma unroll
            for (int mf = 0; mf < MF; mf++)
                ldmatrix_x4(fa[mf], &As[st][wm0 + mf*16 + aRow][ks + aCol]);
#pragma unroll
            for (int p = 0; p < NF/2; p++) {
                uint32_t r[4];
                ldmatrix_x4(r, &Bs[st][wn0 + p*16 + bRow][ks + bCol]);
                fb[2*p  ][0] = r[0]; fb[2*p  ][1] = r[1];
                fb[2*p+1][0] = r[2]; fb[2*p+1][1] = r[3];
            }
#pragma unroll
            for (int mf = 0; mf < MF; mf++)
#pragma unroll
                for (int nf = 0; nf < NF; nf++)
                    mma16816(acc[mf][nf], fa[mf], fb[nf]);
        }
    }

    // epilogue
#pragma unroll
    for (int mf = 0; mf < MF; mf++) {
#pragma unroll
        for (int nf = 0; nf < NF; nf++) {
            int m0 = bm + wm0 + mf*16 + g;
            int n0 = bn + wn0 + nf*8 + 2*tg;
#pragma unroll
            for (int q = 0; q < 4; q++) {
                int m = m0 + (q >> 1) * 8;
                int n = n0 + (q & 1);
                size_t o = (size_t)m * N + n;
                float v = acc[mf][nf][q] + bias[n];
                if (LIF) {
                    float mo = mem[o];
                    float mn = BETA * mo + v - (mo > thr ? thr : 0.f);
                    mem[o] = mn;
                    spkOut[o] = __float2bfloat16((mn - thr) > 0.f ? 1.f : 0.f);
                } else {
                    curOut[o] = v;
                }
            }
        }
    }
}

// ---------------- elementwise LIF for layer 1 ----------------
__global__ void lif_kernel(const float* __restrict__ cur,
                           float* __restrict__ mem,
                           bf16* __restrict__ spk, int n, float thr) {
    int i = blockIdx.x * blockDim.x + threadIdx.x;
    if (i >= n) return;
    float mo = mem[i];
    float mn = BETA * mo + cur[i] - (mo > thr ? thr : 0.f);
    mem[i] = mn;
    spk[i] = __float2bfloat16((mn - thr) > 0.f ? 1.f : 0.f);
}

// ---------------- readout ----------------
__global__ void fcout_kernel(const bf16* __restrict__ s3,
                             const float* __restrict__ Wout,
                             const float* __restrict__ bout,
                             float* __restrict__ mout,
                             float* __restrict__ out_t) {
    const int b   = blockIdx.x;
    const int tid = threadIdx.x;   // 256
    const bf16* sp = s3 + (size_t)b * FEAT;
    float a0 = 0.f, a1 = 0.f, a2 = 0.f, a3 = 0.f;
    for (int k = tid; k < FEAT; k += 256) {
        if (__bfloat162float(sp[k]) != 0.f) {
            a0 += Wout[0 * FEAT + k];
            a1 += Wout[1 * FEAT + k];
            a2 += Wout[2 * FEAT + k];
            a3 += Wout[3 * FEAT + k];
        }
    }
    __shared__ float red[4][256];
    red[0][tid] = a0; red[1][tid] = a1; red[2][tid] = a2; red[3][tid] = a3;
    __syncthreads();
    for (int st = 128; st > 0; st >>= 1) {
        if (tid < st) {
#pragma unroll
            for (int n = 0; n < 4; n++) red[n][tid] += red[n][tid + st];
        }
        __syncthreads();
    }
    if (tid < NCLS) {
        float cur = red[tid][0] + bout[tid];
        float mo  = mout[b * NCLS + tid];
        float mn  = BETA * mo + cur - (mo > 1.0f ? 1.0f : 0.f);
        mout[b * NCLS + tid] = mn;
        out_t[b * NCLS + tid] = (mn - 1.0f) > 0.f ? 1.f : 0.f;
    }
}

// ---------------- host orchestration ----------------
extern "C" void kernel_launch(void* const* d_in, const int* in_sizes, int n_in,
                              void* d_out, int out_size) {
    const float* x     = (const float*)d_in[0];
    const float* W_in  = (const float*)d_in[1];
    const float* b_in  = (const float*)d_in[2];
    const float* W_h1  = (const float*)d_in[3];
    const float* b_h1  = (const float*)d_in[4];
    const float* W_h2  = (const float*)d_in[5];
    const float* b_h2  = (const float*)d_in[6];
    const float* W_out = (const float*)d_in[7];
    const float* b_out = (const float*)d_in[8];
    float* out = (float*)d_out;

    bf16 *Ah, *Am, *Al, *s1, *s2, *s3;
    bf16 *Wih, *Wim, *Wil, *W1h, *W1m, *W1l, *W2h, *W2m, *W2l;
    float *cur1, *m_in, *m_h1, *m_h2, *m_out;
    cudaGetSymbolAddress((void**)&Ah, g_Ah);
    cudaGetSymbolAddress((void**)&Am, g_Am);
    cudaGetSymbolAddress((void**)&Al, g_Al);
    cudaGetSymbolAddress((void**)&cur1, g_cur1);
    cudaGetSymbolAddress((void**)&s1, g_s1);
    cudaGetSymbolAddress((void**)&s2, g_s2);
    cudaGetSymbolAddress((void**)&s3, g_s3);
    cudaGetSymbolAddress((void**)&m_in, g_min);
    cudaGetSymbolAddress((void**)&m_h1, g_mh1);
    cudaGetSymbolAddress((void**)&m_h2, g_mh2);
    cudaGetSymbolAddress((void**)&m_out, g_mout);
    cudaGetSymbolAddress((void**)&Wih, g_Wih);
    cudaGetSymbolAddress((void**)&Wim, g_Wim);
    cudaGetSymbolAddress((void**)&Wil, g_Wil);
    cudaGetSymbolAddress((void**)&W1h, g_W1h);
    cudaGetSymbolAddress((void**)&W1m, g_W1m);
    cudaGetSymbolAddress((void**)&W1l, g_W1l);
    cudaGetSymbolAddress((void**)&W2h, g_W2h);
    cudaGetSymbolAddress((void**)&W2m, g_W2m);
    cudaGetSymbolAddress((void**)&W2l, g_W2l);

    constexpr int SMEM_FC1 = 3 * (128 + 128) * 72 * 2;   // 110592
    constexpr int SMEM_FC2 = 3 * (64 + 128) * 72 * 2;    // 82944
    constexpr int SMEM_FC3 = 3 * (64 + 64) * 72 * 2;     // 55296
    auto kfc1 = mma_gemm<128,128,64,64,32,6,1024,false>;
    auto kfc2 = mma_gemm<64,128,64,32,32,3,512,true>;
    auto kfc3 = mma_gemm<64,64,64,32,32,3,512,true>;
    cudaFuncSetAttribute(kfc1, cudaFuncAttributeMaxDynamicSharedMemorySize, SMEM_FC1);
    cudaFuncSetAttribute(kfc2, cudaFuncAttributeMaxDynamicSharedMemorySize, SMEM_FC2);
    cudaFuncSetAttribute(kfc3, cudaFuncAttributeMaxDynamicSharedMemorySize, SMEM_FC3);

    cudaMemsetAsync(m_in,  0, (size_t)MROWS * H0 * sizeof(float));
    cudaMemsetAsync(m_h1,  0, (size_t)MROWS * H1 * sizeof(float));
    cudaMemsetAsync(m_h2,  0, (size_t)MROWS * H2 * sizeof(float));
    cudaMemsetAsync(m_out, 0, (size_t)BATCH * NCLS * sizeof(float));

    wsplit_kernel<<<(H0*INDIM + 255)/256, 256>>>(W_in, H0*INDIM, Wih, Wim, Wil);
    wsplit_kernel<<<(H1*H0   + 255)/256, 256>>>(W_h1, H1*H0,   W1h, W1m, W1l);
    wsplit_kernel<<<(H2*H1   + 255)/256, 256>>>(W_h2, H2*H1,   W2h, W2m, W2l);

    pool_kernel<<<(MALL*INDIM + 255)/256, 256>>>(x);

    // fc1 all timesteps: 6-term exact bf16 split GEMM
    {
        Terms t1;
        t1.A[0]=Ah;  t1.B[0]=Wih;
        t1.A[1]=Ah;  t1.B[1]=Wim;
        t1.A[2]=Am;  t1.B[2]=Wih;
        t1.A[3]=Ah;  t1.B[3]=Wil;
        t1.A[4]=Am;  t1.B[4]=Wim;
        t1.A[5]=Al;  t1.B[5]=Wih;
        dim3 grid(H0/128, MALL/128);
        kfc1<<<grid, 256, SMEM_FC1>>>(t1, b_in, cur1, nullptr, nullptr,
                                      MALL, H0, 0.f);
    }

    for (int t = 0; t < TSTEPS; t++) {
        lif_kernel<<<(MROWS*H0 + 255)/256, 256>>>(
            cur1 + (size_t)t * MROWS * H0, m_in, s1, MROWS*H0, 0.5f);

        Terms t2;
        t2.A[0]=s1; t2.B[0]=W1h;
        t2.A[1]=s1; t2.B[1]=W1m;
        t2.A[2]=s1; t2.B[2]=W1l;
        t2.A[3]=t2.A[4]=t2.A[5]=s1; t2.B[3]=t2.B[4]=t2.B[5]=W1h;
        kfc2<<<dim3(H1/128, MROWS/64), 256, SMEM_FC2>>>(
            t2, b_h1, nullptr, s2, m_h1, MROWS, H1, 0.5f);

        Terms t3;
        t3.A[0]=s2; t3.B[0]=W2h;
        t3.A[1]=s2; t3.B[1]=W2m;
        t3.A[2]=s2; t3.B[2]=W2l;
        t3.A[3]=t3.A[4]=t3.A[5]=s2; t3.B[3]=t3.B[4]=t3.B[5]=W2h;
        kfc3<<<dim3(H2/64, MROWS/64), 128, SMEM_FC3>>>(
            t3, b_h2, nullptr, s3, m_h2, MROWS, H2, 0.5f);

        fcout_kernel<<<BATCH, 256>>>(s3, W_out, b_out, m_out,
                                     out + (size_t)t * BATCH * NCLS);
    }
}

// round 5
// speedup vs baseline: 2.1468x; 1.5286x over previous
#include <cuda_runtime.h>
#include <cuda_bf16.h>
#include <cstdint>
#include <cstddef>

typedef __nv_bfloat16 bf16;

// ---------------- problem constants ----------------
#define TSTEPS 8
#define BATCH  64
#define CC     3
#define NWIN   232
#define HH     64
#define WW     64
#define CHUNK  29
#define DPP    13
#define INDIM  1024
#define H0     512
#define H1     512
#define H2     256
#define CD     39
#define FEAT   9984
#define NCLS   4
#define MROWS  (BATCH*CD)        // 2496
#define MALL   (TSTEPS*MROWS)    // 19968
#define BETA   0.9f

// ---------------- scratch (static device memory) ----------------
__device__ bf16  g_Ah[(size_t)MALL * INDIM];
__device__ bf16  g_Am[(size_t)MALL * INDIM];
__device__ bf16  g_Al[(size_t)MALL * INDIM];
__device__ float g_cur1[(size_t)MALL * H0];      // reused for cur2
__device__ float g_cur3[(size_t)MALL * H2];
__device__ bf16  g_s1[(size_t)MALL * H0];
__device__ bf16  g_s2[(size_t)MALL * H1];
__device__ bf16  g_s3[(size_t)MALL * H2];
__device__ float g_curout[TSTEPS * BATCH * NCLS];
__device__ bf16 g_Wih[H0 * INDIM], g_Wim[H0 * INDIM], g_Wil[H0 * INDIM];
__device__ bf16 g_W1h[H1 * H0],    g_W1m[H1 * H0],    g_W1l[H1 * H0];
__device__ bf16 g_W2h[H2 * H1],    g_W2m[H2 * H1],    g_W2l[H2 * H1];

// ---------------- exact fp32 -> 3x bf16 split ----------------
__device__ __forceinline__ void split3(float a, bf16& h, bf16& m, bf16& l) {
    h = __float2bfloat16(a);
    float r = a - __bfloat162float(h);     // exact
    m = __float2bfloat16(r);
    float r2 = r - __bfloat162float(m);    // exact
    l = __float2bfloat16(r2);
}

__global__ void wsplit_kernel(const float* __restrict__ w, int n,
                              bf16* __restrict__ h, bf16* __restrict__ m,
                              bf16* __restrict__ l) {
    int i = blockIdx.x * blockDim.x + threadIdx.x;
    if (i >= n) return;
    bf16 a, b, c;
    split3(w[i], a, b, c);
    h[i] = a; m[i] = b; l[i] = c;
}

// ---------------- avg-pool3d fused with A-matrix 3-split ----------------
__global__ void pool_kernel(const float* __restrict__ x) {
    int idx = blockIdx.x * blockDim.x + threadIdx.x;
    if (idx >= MALL * INDIM) return;
    int hw = idx & (INDIM - 1);
    int r  = idx >> 10;
    int cd = r % CD;
    int tb = r / CD;
    int b  = tb % BATCH;
    int t  = tb / BATCH;
    int c  = cd / DPP;
    int dp = cd % DPP;
    int hp = hw >> 5;
    int wp = hw & 31;
    int d0 = t * CHUNK + 2 * dp;
    const float* base = x + (((size_t)b * CC + c) * NWIN) * (HH * WW)
                          + (size_t)(2 * hp) * WW + (size_t)(2 * wp);
    float s = 0.f;
#pragma unroll
    for (int kd = 0; kd < 4; kd++) {
        const float* p = base + (size_t)(d0 + kd) * (HH * WW);
        float2 r0 = *(const float2*)(p);
        float2 r1 = *(const float2*)(p + WW);
        s += (r0.x + r0.y) + (r1.x + r1.y);
    }
    s *= (1.0f / 16.0f);
    bf16 hb, mb, lb;
    split3(s, hb, mb, lb);
    g_Ah[idx] = hb; g_Am[idx] = mb; g_Al[idx] = lb;
}

// ---------------- cp.async / ldmatrix helpers ----------------
__device__ __forceinline__ void cpasync16(void* s, const void* g) {
    uint32_t sa = (uint32_t)__cvta_generic_to_shared(s);
    asm volatile("cp.async.cg.shared.global [%0], [%1], 16;\n" :: "r"(sa), "l"(g));
}
__device__ __forceinline__ void cp_commit() {
    asm volatile("cp.async.commit_group;\n");
}
template<int N> __device__ __forceinline__ void cp_wait() {
    asm volatile("cp.async.wait_group %0;\n" :: "n"(N));
}
__device__ __forceinline__ void ldmatrix_x4(uint32_t* r, const void* p) {
    uint32_t a = (uint32_t)__cvta_generic_to_shared(p);
    asm volatile("ldmatrix.sync.aligned.m8n8.x4.shared.b16 {%0,%1,%2,%3}, [%4];\n"
        : "=r"(r[0]), "=r"(r[1]), "=r"(r[2]), "=r"(r[3]) : "r"(a));
}

// ---------------- bf16 tensor-core multi-term GEMM, 3-stage pipeline ------
struct Terms {
    const bf16* A[6];
    const bf16* B[6];
};

__device__ __forceinline__ void mma16816(float* c, const uint32_t* a, const uint32_t* b) {
    asm volatile(
        "mma.sync.aligned.m16n8k16.row.col.f32.bf16.bf16.f32 "
        "{%0,%1,%2,%3},{%4,%5,%6,%7},{%8,%9},{%0,%1,%2,%3};\n"
        : "+f"(c[0]), "+f"(c[1]), "+f"(c[2]), "+f"(c[3])
        : "r"(a[0]), "r"(a[1]), "r"(a[2]), "r"(a[3]), "r"(b[0]), "r"(b[1]));
}

template<int BM, int BN, int BK, int WM, int WN, int NT, int K>
__global__ void __launch_bounds__((BM/WM)*(BN/WN)*32)
mma_gemm(Terms terms, const float* __restrict__ bias,
         float* __restrict__ curOut, int M, int N) {
    constexpr int NWARP   = (BM/WM)*(BN/WN);
    constexpr int THREADS = NWARP * 32;
    constexpr int PAD     = 8;
    constexpr int LDW     = BK + PAD;
    constexpr int STAGES  = 3;
    constexpr int KT      = K / BK;
    constexpr int NTILE   = NT * KT;
    constexpr int MF = WM / 16, NF = WN / 8;
    static_assert(NF % 2 == 0, "NF even for paired ldmatrix");
    constexpr int AIT = (BM * BK / 8) / THREADS;
    constexpr int BIT = (BN * BK / 8) / THREADS;
    static_assert(AIT >= 1 && BIT >= 1, "tile load");

    extern __shared__ char dynsmem[];
    bf16 (*As)[BM][LDW] = (bf16(*)[BM][LDW])dynsmem;
    bf16 (*Bs)[BN][LDW] = (bf16(*)[BN][LDW])(dynsmem + (size_t)STAGES * BM * LDW * 2);

    const int tid  = threadIdx.x;
    const int lane = tid & 31;
    const int warp = tid >> 5;
    const int g    = lane >> 2;
    const int tg   = lane & 3;
    const int wn0  = (warp % (BN/WN)) * WN;
    const int wm0  = (warp / (BN/WN)) * WM;
    const int bm   = blockIdx.y * BM;
    const int bn   = blockIdx.x * BN;

    const int l8   = lane & 7;
    const int aRow = ((lane >> 3) & 1) * 8 + l8;
    const int aCol = (lane >> 4) * 8;
    const int bRow = (lane >> 4) * 8 + l8;
    const int bCol = ((lane >> 3) & 1) * 8;

    const int lr = tid / (BK/8);
    const int lc = (tid % (BK/8)) * 8;
    constexpr int AROWS = THREADS / (BK/8);

    auto load_tile = [&](int i, int s) {
        const int term = i / KT;
        const int k0   = (i % KT) * BK;
        const bf16* __restrict__ Ag = terms.A[term] + (size_t)bm * K + k0;
        const bf16* __restrict__ Bg = terms.B[term] + (size_t)bn * K + k0;
#pragma unroll
        for (int it = 0; it < AIT; it++)
            cpasync16(&As[s][lr + it*AROWS][lc], Ag + (size_t)(lr + it*AROWS) * K + lc);
#pragma unroll
        for (int it = 0; it < BIT; it++)
            cpasync16(&Bs[s][lr + it*AROWS][lc], Bg + (size_t)(lr + it*AROWS) * K + lc);
        cp_commit();
    };

    float acc[MF][NF][4];
#pragma unroll
    for (int i = 0; i < MF; i++)
#pragma unroll
        for (int j = 0; j < NF; j++)
#pragma unroll
            for (int q = 0; q < 4; q++) acc[i][j][q] = 0.f;

#pragma unroll
    for (int i = 0; i < STAGES - 1; i++) load_tile(i, i);

    for (int i = 0; i < NTILE; i++) {
        cp_wait<STAGES - 2>();
        __syncthreads();
        const int nxt = i + STAGES - 1;
        if (nxt < NTILE) load_tile(nxt, nxt % STAGES);
        const int st = i % STAGES;
#pragma unroll
        for (int ks = 0; ks < BK; ks += 16) {
            uint32_t fa[MF][4], fb[NF][2];
#pragma unroll
            for (int mf = 0; mf < MF; mf++)
                ldmatrix_x4(fa[mf], &As[st][wm0 + mf*16 + aRow][ks + aCol]);
#pragma unroll
            for (int p = 0; p < NF/2; p++) {
                uint32_t r[4];
                ldmatrix_x4(r, &Bs[st][wn0 + p*16 + bRow][ks + bCol]);
                fb[2*p  ][0] = r[0]; fb[2*p  ][1] = r[1];
                fb[2*p+1][0] = r[2]; fb[2*p+1][1] = r[3];
            }
#pragma unroll
            for (int mf = 0; mf < MF; mf++)
#pragma unroll
                for (int nf = 0; nf < NF; nf++)
                    mma16816(acc[mf][nf], fa[mf], fb[nf]);
        }
    }

#pragma unroll
    for (int mf = 0; mf < MF; mf++) {
#pragma unroll
        for (int nf = 0; nf < NF; nf++) {
            int m0 = bm + wm0 + mf*16 + g;
            int n0 = bn + wn0 + nf*8 + 2*tg;
#pragma unroll
            for (int q = 0; q < 4; q++) {
                int m = m0 + (q >> 1) * 8;
                int n = n0 + (q & 1);
                curOut[(size_t)m * N + n] = acc[mf][nf][q] + bias[n];
            }
        }
    }
}

// ---------------- LIF time-scan: membrane in register, 8 steps ------------
// cur laid out [t][state] with n states per timestep; spikes to [t][state].
__global__ void lif_scan_kernel(const float* __restrict__ cur,
                                bf16* __restrict__ spk, int n, float thr) {
    int i = blockIdx.x * blockDim.x + threadIdx.x;
    if (i >= n) return;
    float m = 0.f;
#pragma unroll
    for (int t = 0; t < TSTEPS; t++) {
        float reset = (m > thr) ? thr : 0.f;
        m = BETA * m + cur[(size_t)t * n + i] - reset;
        spk[(size_t)t * n + i] = __float2bfloat16((m - thr) > 0.f ? 1.f : 0.f);
    }
}

// ---------------- readout currents: (t,b) row x Wout (4 x 9984) ----------
__global__ void fcout_kernel(const bf16* __restrict__ s3,
                             const float* __restrict__ Wout,
                             const float* __restrict__ bout,
                             float* __restrict__ curout) {
    const int tb  = blockIdx.x;          // t*BATCH + b
    const int t   = tb / BATCH;
    const int b   = tb % BATCH;
    const int tid = threadIdx.x;         // 256
    const bf16* sp = s3 + ((size_t)t * MROWS + (size_t)b * CD) * H2;  // FEAT contiguous
    float a0 = 0.f, a1 = 0.f, a2 = 0.f, a3 = 0.f;
    for (int k = tid; k < FEAT; k += 256) {
        if (__bfloat162float(sp[k]) != 0.f) {
            a0 += Wout[0 * FEAT + k];
            a1 += Wout[1 * FEAT + k];
            a2 += Wout[2 * FEAT + k];
            a3 += Wout[3 * FEAT + k];
        }
    }
    __shared__ float red[4][256];
    red[0][tid] = a0; red[1][tid] = a1; red[2][tid] = a2; red[3][tid] = a3;
    __syncthreads();
    for (int st = 128; st > 0; st >>= 1) {
        if (tid < st) {
#pragma unroll
            for (int n = 0; n < 4; n++) red[n][tid] += red[n][tid + st];
        }
        __syncthreads();
    }
    if (tid < NCLS)
        curout[(size_t)tb * NCLS + tid] = red[tid][0] + bout[tid];
}

// ---------------- output LIF scan (thr = 1.0), writes final spikes -------
__global__ void lifout_kernel(const float* __restrict__ curout,
                              float* __restrict__ out) {
    int i = threadIdx.x;                 // BATCH*NCLS = 256
    float m = 0.f;
#pragma unroll
    for (int t = 0; t < TSTEPS; t++) {
        float reset = (m > 1.0f) ? 1.0f : 0.f;
        m = BETA * m + curout[t * BATCH * NCLS + i] - reset;
        out[t * BATCH * NCLS + i] = (m - 1.0f) > 0.f ? 1.f : 0.f;
    }
}

// ---------------- host orchestration ----------------
extern "C" void kernel_launch(void* const* d_in, const int* in_sizes, int n_in,
                              void* d_out, int out_size) {
    const float* x     = (const float*)d_in[0];
    const float* W_in  = (const float*)d_in[1];
    const float* b_in  = (const float*)d_in[2];
    const float* W_h1  = (const float*)d_in[3];
    const float* b_h1  = (const float*)d_in[4];
    const float* W_h2  = (const float*)d_in[5];
    const float* b_h2  = (const float*)d_in[6];
    const float* W_out = (const float*)d_in[7];
    const float* b_out = (const float*)d_in[8];
    float* out = (float*)d_out;

    bf16 *Ah, *Am, *Al, *s1, *s2, *s3;
    bf16 *Wih, *Wim, *Wil, *W1h, *W1m, *W1l, *W2h, *W2m, *W2l;
    float *cur12, *cur3, *curout;
    cudaGetSymbolAddress((void**)&Ah, g_Ah);
    cudaGetSymbolAddress((void**)&Am, g_Am);
    cudaGetSymbolAddress((void**)&Al, g_Al);
    cudaGetSymbolAddress((void**)&cur12, g_cur1);
    cudaGetSymbolAddress((void**)&cur3, g_cur3);
    cudaGetSymbolAddress((void**)&curout, g_curout);
    cudaGetSymbolAddress((void**)&s1, g_s1);
    cudaGetSymbolAddress((void**)&s2, g_s2);
    cudaGetSymbolAddress((void**)&s3, g_s3);
    cudaGetSymbolAddress((void**)&Wih, g_Wih);
    cudaGetSymbolAddress((void**)&Wim, g_Wim);
    cudaGetSymbolAddress((void**)&Wil, g_Wil);
    cudaGetSymbolAddress((void**)&W1h, g_W1h);
    cudaGetSymbolAddress((void**)&W1m, g_W1m);
    cudaGetSymbolAddress((void**)&W1l, g_W1l);
    cudaGetSymbolAddress((void**)&W2h, g_W2h);
    cudaGetSymbolAddress((void**)&W2m, g_W2m);
    cudaGetSymbolAddress((void**)&W2l, g_W2l);

    constexpr int SMEM = 3 * (128 + 128) * 72 * 2;   // 110592
    auto kfc1 = mma_gemm<128,128,64,64,32,6,1024>;
    auto kfc2 = mma_gemm<128,128,64,64,32,3,512>;
    cudaFuncSetAttribute(kfc1, cudaFuncAttributeMaxDynamicSharedMemorySize, SMEM);
    cudaFuncSetAttribute(kfc2, cudaFuncAttributeMaxDynamicSharedMemorySize, SMEM);

    wsplit_kernel<<<(H0*INDIM + 255)/256, 256>>>(W_in, H0*INDIM, Wih, Wim, Wil);
    wsplit_kernel<<<(H1*H0   + 255)/256, 256>>>(W_h1, H1*H0,   W1h, W1m, W1l);
    wsplit_kernel<<<(H2*H1   + 255)/256, 256>>>(W_h2, H2*H1,   W2h, W2m, W2l);

    pool_kernel<<<(MALL*INDIM + 255)/256, 256>>>(x);

    // fc1 all timesteps: 6-term exact bf16 split GEMM  (19968x1024 -> 512)
    {
        Terms t1;
        t1.A[0]=Ah;  t1.B[0]=Wih;
        t1.A[1]=Ah;  t1.B[1]=Wim;
        t1.A[2]=Am;  t1.B[2]=Wih;
        t1.A[3]=Ah;  t1.B[3]=Wil;
        t1.A[4]=Am;  t1.B[4]=Wim;
        t1.A[5]=Al;  t1.B[5]=Wih;
        kfc1<<<dim3(H0/128, MALL/128), 256, SMEM>>>(t1, b_in, cur12, MALL, H0);
    }
    // layer-1 LIF scan over all 8 timesteps (membrane in register)
    lif_scan_kernel<<<(MROWS*H0 + 255)/256, 256>>>(cur12, s1, MROWS*H0, 0.5f);

    // fc2 all timesteps: 3-term spike GEMM (19968x512 -> 512)
    {
        Terms t2;
        t2.A[0]=s1; t2.B[0]=W1h;
        t2.A[1]=s1; t2.B[1]=W1m;
        t2.A[2]=s1; t2.B[2]=W1l;
        t2.A[3]=t2.A[4]=t2.A[5]=s1; t2.B[3]=t2.B[4]=t2.B[5]=W1h;
        kfc2<<<dim3(H1/128, MALL/128), 256, SMEM>>>(t2, b_h1, cur12, MALL, H1);
    }
    lif_scan_kernel<<<(MROWS*H1 + 255)/256, 256>>>(cur12, s2, MROWS*H1, 0.5f);

    // fc3 all timesteps: 3-term spike GEMM (19968x512 -> 256)
    {
        Terms t3;
        t3.A[0]=s2; t3.B[0]=W2h;
        t3.A[1]=s2; t3.B[1]=W2m;
        t3.A[2]=s2; t3.B[2]=W2l;
        t3.A[3]=t3.A[4]=t3.A[5]=s2; t3.B[3]=t3.B[4]=t3.B[5]=W2h;
        kfc2<<<dim3(H2/128, MALL/128), 256, SMEM>>>(t3, b_h2, cur3, MALL, H2);
    }
    lif_scan_kernel<<<(MROWS*H2 + 255)/256, 256>>>(cur3, s3, MROWS*H2, 0.5f);

    // readout currents for all (t,b), then output LIF scan
    fcout_kernel<<<TSTEPS*BATCH, 256>>>(s3, W_out, b_out, curout);
    lifout_kernel<<<1, BATCH*NCLS>>>(curout, out);
}

// round 7
// speedup vs baseline: 2.1662x; 1.0091x over previous
#include <cuda_runtime.h>
#include <cuda_bf16.h>
#include <cstdint>
#include <cstddef>

typedef __nv_bfloat16 bf16;

// ---------------- problem constants ----------------
#define TSTEPS 8
#define BATCH  64
#define CC     3
#define NWIN   232
#define HH     64
#define WW     64
#define CHUNK  29
#define DPP    13
#define INDIM  1024
#define H0     512
#define H1     512
#define H2     256
#define CD     39
#define FEAT   9984
#define NCLS   4
#define MROWS  (BATCH*CD)        // 2496
#define MALL   (TSTEPS*MROWS)    // 19968
#define BETA   0.9f

// ---------------- scratch (static device memory) ----------------
__device__ bf16  g_Ah[(size_t)MALL * INDIM];
__device__ bf16  g_Am[(size_t)MALL * INDIM];
__device__ bf16  g_Al[(size_t)MALL * INDIM];
__device__ float g_cur1[(size_t)MALL * H0];      // reused for cur2
__device__ float g_cur3[(size_t)MALL * H2];
__device__ bf16  g_s1[(size_t)MALL * H0];
__device__ bf16  g_s2[(size_t)MALL * H1];
__device__ bf16  g_s3[(size_t)MALL * H2];
__device__ float g_curout[TSTEPS * BATCH * NCLS];
__device__ bf16 g_Wih[H0 * INDIM], g_Wim[H0 * INDIM], g_Wil[H0 * INDIM];
__device__ bf16 g_W1h[H1 * H0],    g_W1m[H1 * H0],    g_W1l[H1 * H0];
__device__ bf16 g_W2h[H2 * H1],    g_W2m[H2 * H1],    g_W2l[H2 * H1];

// ---------------- exact fp32 -> 3x bf16 split ----------------
__device__ __forceinline__ void split3(float a, bf16& h, bf16& m, bf16& l) {
    h = __float2bfloat16(a);
    float r = a - __bfloat162float(h);     // exact
    m = __float2bfloat16(r);
    float r2 = r - __bfloat162float(m);    // exact
    l = __float2bfloat16(r2);
}

__global__ void wsplit_kernel(const float* __restrict__ w, int n,
                              bf16* __restrict__ h, bf16* __restrict__ m,
                              bf16* __restrict__ l) {
    int i = blockIdx.x * blockDim.x + threadIdx.x;
    if (i >= n) return;
    bf16 a, b, c;
    split3(w[i], a, b, c);
    h[i] = a; m[i] = b; l[i] = c;
}

// ---------------- avg-pool3d fused with A-matrix 3-split ----------------
__global__ void pool_kernel(const float* __restrict__ x) {
    int idx = blockIdx.x * blockDim.x + threadIdx.x;
    if (idx >= MALL * INDIM) return;
    int hw = idx & (INDIM - 1);
    int r  = idx >> 10;
    int cd = r % CD;
    int tb = r / CD;
    int b  = tb % BATCH;
    int t  = tb / BATCH;
    int c  = cd / DPP;
    int dp = cd % DPP;
    int hp = hw >> 5;
    int wp = hw & 31;
    int d0 = t * CHUNK + 2 * dp;
    const float* base = x + (((size_t)b * CC + c) * NWIN) * (HH * WW)
                          + (size_t)(2 * hp) * WW + (size_t)(2 * wp);
    float s = 0.f;
#pragma unroll
    for (int kd = 0; kd < 4; kd++) {
        const float* p = base + (size_t)(d0 + kd) * (HH * WW);
        float2 r0 = *(const float2*)(p);
        float2 r1 = *(const float2*)(p + WW);
        s += (r0.x + r0.y) + (r1.x + r1.y);
    }
    s *= (1.0f / 16.0f);
    bf16 hb, mb, lb;
    split3(s, hb, mb, lb);
    g_Ah[idx] = hb; g_Am[idx] = mb; g_Al[idx] = lb;
}

// ---------------- cp.async / ldmatrix helpers ----------------
__device__ __forceinline__ void cpasync16(void* s, const void* g) {
    uint32_t sa = (uint32_t)__cvta_generic_to_shared(s);
    asm volatile("cp.async.cg.shared.global [%0], [%1], 16;\n" :: "r"(sa), "l"(g));
}
__device__ __forceinline__ void cp_commit() {
    asm volatile("cp.async.commit_group;\n");
}
template<int N> __device__ __forceinline__ void cp_wait() {
    asm volatile("cp.async.wait_group %0;\n" :: "n"(N));
}
__device__ __forceinline__ void ldmatrix_x4(uint32_t* r, const void* p) {
    uint32_t a = (uint32_t)__cvta_generic_to_shared(p);
    asm volatile("ldmatrix.sync.aligned.m8n8.x4.shared.b16 {%0,%1,%2,%3}, [%4];\n"
        : "=r"(r[0]), "=r"(r[1]), "=r"(r[2]), "=r"(r[3]) : "r"(a));
}

// ---------------- bf16 tensor-core multi-term GEMM, 3-stage pipeline ------
struct Terms {
    const bf16* A[6];
    const bf16* B[6];
};

__device__ __forceinline__ void mma16816(float* c, const uint32_t* a, const uint32_t* b) {
    asm volatile(
        "mma.sync.aligned.m16n8k16.row.col.f32.bf16.bf16.f32 "
        "{%0,%1,%2,%3},{%4,%5,%6,%7},{%8,%9},{%0,%1,%2,%3};\n"
        : "+f"(c[0]), "+f"(c[1]), "+f"(c[2]), "+f"(c[3])
        : "r"(a[0]), "r"(a[1]), "r"(a[2]), "r"(a[3]), "r"(b[0]), "r"(b[1]));
}

// BM=BN=128, BK=64, 4 warps, warp tile 64x64, 3-stage cp.async, 2 CTAs/SM.
template<int NT, int K>
__global__ void __launch_bounds__(128, 2)
mma_gemm(Terms terms, const float* __restrict__ bias,
         float* __restrict__ curOut, int N) {
    constexpr int BM = 128, BN = 128, BK = 64;
    constexpr int WM = 64,  WN = 64;
    constexpr int PAD = 8, LDW = BK + PAD;
    constexpr int STAGES = 3;
    constexpr int KT = K / BK;
    constexpr int NTILE = NT * KT;
    constexpr int MF = WM / 16, NF = WN / 8;   // 4, 8

    extern __shared__ char dynsmem[];
    bf16 (*As)[BM][LDW] = (bf16(*)[BM][LDW])dynsmem;
    bf16 (*Bs)[BN][LDW] = (bf16(*)[BN][LDW])(dynsmem + (size_t)STAGES * BM * LDW * 2);

    const int tid  = threadIdx.x;
    const int lane = tid & 31;
    const int warp = tid >> 5;
    const int g    = lane >> 2;
    const int tg   = lane & 3;
    const int wn0  = (warp & 1) * WN;
    const int wm0  = (warp >> 1) * WM;
    const int bm   = blockIdx.y * BM;
    const int bn   = blockIdx.x * BN;

    const int l8   = lane & 7;
    const int aRow = ((lane >> 3) & 1) * 8 + l8;
    const int aCol = (lane >> 4) * 8;
    const int bRow = (lane >> 4) * 8 + l8;
    const int bCol = ((lane >> 3) & 1) * 8;

    // loader: BK=64 -> 8 x 16B chunks per row; 128 threads -> 16 rows/pass
    const int lr = tid >> 3;
    const int lc = (tid & 7) * 8;

    auto load_tile = [&](int i, int s) {
        const int term = i / KT;
        const int k0   = (i % KT) * BK;
        const bf16* __restrict__ Ag = terms.A[term] + (size_t)bm * K + k0;
        const bf16* __restrict__ Bg = terms.B[term] + (size_t)bn * K + k0;
#pragma unroll
        for (int it = 0; it < 8; it++)
            cpasync16(&As[s][lr + it*16][lc], Ag + (size_t)(lr + it*16) * K + lc);
#pragma unroll
        for (int it = 0; it < 8; it++)
            cpasync16(&Bs[s][lr + it*16][lc], Bg + (size_t)(lr + it*16) * K + lc);
        cp_commit();
    };

    float acc[MF][NF][4];
#pragma unroll
    for (int i = 0; i < MF; i++)
#pragma unroll
        for (int j = 0; j < NF; j++)
#pragma unroll
            for (int q = 0; q < 4; q++) acc[i][j][q] = 0.f;

#pragma unroll
    for (int i = 0; i < STAGES - 1; i++) load_tile(i, i);

    for (int i = 0; i < NTILE; i++) {
        cp_wait<STAGES - 2>();
        __syncthreads();
        const int nxt = i + STAGES - 1;
        if (nxt < NTILE) load_tile(nxt, nxt % STAGES);
        const int st = i % STAGES;
#pragma unroll
        for (int ks = 0; ks < BK; ks += 16) {
            uint32_t fa[MF][4], fb[NF][2];
#pragma unroll
            for (int mf = 0; mf < MF; mf++)
                ldmatrix_x4(fa[mf], &As[st][wm0 + mf*16 + aRow][ks + aCol]);
#pragma unroll
            for (int p = 0; p < NF/2; p++) {
                uint32_t r[4];
                ldmatrix_x4(r, &Bs[st][wn0 + p*16 + bRow][ks + bCol]);
                fb[2*p  ][0] = r[0]; fb[2*p  ][1] = r[1];
                fb[2*p+1][0] = r[2]; fb[2*p+1][1] = r[3];
            }
#pragma unroll
            for (int mf = 0; mf < MF; mf++)
#pragma unroll
                for (int nf = 0; nf < NF; nf++)
                    mma16816(acc[mf][nf], fa[mf], fb[nf]);
        }
    }

    // epilogue: fp32 currents + bias
#pragma unroll
    for (int mf = 0; mf < MF; mf++) {
#pragma unroll
        for (int nf = 0; nf < NF; nf++) {
            int m0 = bm + wm0 + mf*16 + g;
            int n0 = bn + wn0 + nf*8 + 2*tg;
#pragma unroll
            for (int q = 0; q < 4; q++) {
                int m = m0 + (q >> 1) * 8;
                int n = n0 + (q & 1);
                curOut[(size_t)m * N + n] = acc[mf][nf][q] + bias[n];
            }
        }
    }
}

// ---------------- LIF time-scan: membrane in register, 8 steps ------------
__global__ void lif_scan_kernel(const float* __restrict__ cur,
                                bf16* __restrict__ spk, int n, float thr) {
    int i = blockIdx.x * blockDim.x + threadIdx.x;
    if (i >= n) return;
    float m = 0.f;
#pragma unroll
    for (int t = 0; t < TSTEPS; t++) {
        float reset = (m > thr) ? thr : 0.f;
        m = BETA * m + cur[(size_t)t * n + i] - reset;
        spk[(size_t)t * n + i] = __float2bfloat16((m - thr) > 0.f ? 1.f : 0.f);
    }
}

// ---------------- readout currents: (t,b) row x Wout (4 x 9984) ----------
__global__ void fcout_kernel(const bf16* __restrict__ s3,
                             const float* __restrict__ Wout,
                             const float* __restrict__ bout,
                             float* __restrict__ curout) {
    const int tb  = blockIdx.x;          // t*BATCH + b
    const int t   = tb / BATCH;
    const int b   = tb % BATCH;
    const int tid = threadIdx.x;         // 256
    const bf16* sp = s3 + ((size_t)t * MROWS + (size_t)b * CD) * H2;
    float a0 = 0.f, a1 = 0.f, a2 = 0.f, a3 = 0.f;
    for (int k = tid; k < FEAT; k += 256) {
        if (__bfloat162float(sp[k]) != 0.f) {
            a0 += Wout[0 * FEAT + k];
            a1 += Wout[1 * FEAT + k];
            a2 += Wout[2 * FEAT + k];
            a3 += Wout[3 * FEAT + k];
        }
    }
    __shared__ float red[4][256];
    red[0][tid] = a0; red[1][tid] = a1; red[2][tid] = a2; red[3][tid] = a3;
    __syncthreads();
    for (int st = 128; st > 0; st >>= 1) {
        if (tid < st) {
#pragma unroll
            for (int n = 0; n < 4; n++) red[n][tid] += red[n][tid + st];
        }
        __syncthreads();
    }
    if (tid < NCLS)
        curout[(size_t)tb * NCLS + tid] = red[tid][0] + bout[tid];
}

// ---------------- output LIF scan (thr = 1.0) ----------------------------
__global__ void lifout_kernel(const float* __restrict__ curout,
                              float* __restrict__ out) {
    int i = threadIdx.x;                 // BATCH*NCLS = 256
    float m = 0.f;
#pragma unroll
    for (int t = 0; t < TSTEPS; t++) {
        float reset = (m > 1.0f) ? 1.0f : 0.f;
        m = BETA * m + curout[t * BATCH * NCLS + i] - reset;
        out[t * BATCH * NCLS + i] = (m - 1.0f) > 0.f ? 1.f : 0.f;
    }
}

// ---------------- host orchestration ----------------
extern "C" void kernel_launch(void* const* d_in, const int* in_sizes, int n_in,
                              void* d_out, int out_size) {
    const float* x     = (const float*)d_in[0];
    const float* W_in  = (const float*)d_in[1];
    const float* b_in  = (const float*)d_in[2];
    const float* W_h1  = (const float*)d_in[3];
    const float* b_h1  = (const float*)d_in[4];
    const float* W_h2  = (const float*)d_in[5];
    const float* b_h2  = (const float*)d_in[6];
    const float* W_out = (const float*)d_in[7];
    const float* b_out = (const float*)d_in[8];
    float* out = (float*)d_out;

    bf16 *Ah, *Am, *Al, *s1, *s2, *s3;
    bf16 *Wih, *Wim, *Wil, *W1h, *W1m, *W1l, *W2h, *W2m, *W2l;
    float *cur12, *cur3, *curout;
    cudaGetSymbolAddress((void**)&Ah, g_Ah);
    cudaGetSymbolAddress((void**)&Am, g_Am);
    cudaGetSymbolAddress((void**)&Al, g_Al);
    cudaGetSymbolAddress((void**)&cur12, g_cur1);
    cudaGetSymbolAddress((void**)&cur3, g_cur3);
    cudaGetSymbolAddress((void**)&curout, g_curout);
    cudaGetSymbolAddress((void**)&s1, g_s1);
    cudaGetSymbolAddress((void**)&s2, g_s2);
    cudaGetSymbolAddress((void**)&s3, g_s3);
    cudaGetSymbolAddress((void**)&Wih, g_Wih);
    cudaGetSymbolAddress((void**)&Wim, g_Wim);
    cudaGetSymbolAddress((void**)&Wil, g_Wil);
    cudaGetSymbolAddress((void**)&W1h, g_W1h);
    cudaGetSymbolAddress((void**)&W1m, g_W1m);
    cudaGetSymbolAddress((void**)&W1l, g_W1l);
    cudaGetSymbolAddress((void**)&W2h, g_W2h);
    cudaGetSymbolAddress((void**)&W2m, g_W2m);
    cudaGetSymbolAddress((void**)&W2l, g_W2l);

    // smem: 3 stages * (128 + 128) rows * 72 elems * 2B = 110592
    constexpr int SMEM = 3 * (128 + 128) * 72 * 2;
    auto kfc1 = mma_gemm<6, 1024>;
    auto kfc23 = mma_gemm<3, 512>;
    cudaFuncSetAttribute(kfc1,  cudaFuncAttributeMaxDynamicSharedMemorySize, SMEM);
    cudaFuncSetAttribute(kfc23, cudaFuncAttributeMaxDynamicSharedMemorySize, SMEM);

    wsplit_kernel<<<(H0*INDIM + 255)/256, 256>>>(W_in, H0*INDIM, Wih, Wim, Wil);
    wsplit_kernel<<<(H1*H0   + 255)/256, 256>>>(W_h1, H1*H0,   W1h, W1m, W1l);
    wsplit_kernel<<<(H2*H1   + 255)/256, 256>>>(W_h2, H2*H1,   W2h, W2m, W2l);

    pool_kernel<<<(MALL*INDIM + 255)/256, 256>>>(x);

    // fc1: 6-term exact bf16 split GEMM  (19968x1024 -> 512)
    {
        Terms t1;
        t1.A[0]=Ah;  t1.B[0]=Wih;
        t1.A[1]=Ah;  t1.B[1]=Wim;
        t1.A[2]=Am;  t1.B[2]=Wih;
        t1.A[3]=Ah;  t1.B[3]=Wil;
        t1.A[4]=Am;  t1.B[4]=Wim;
        t1.A[5]=Al;  t1.B[5]=Wih;
        kfc1<<<dim3(H0/128, MALL/128), 128, SMEM>>>(t1, b_in, cur12, H0);
    }
    lif_scan_kernel<<<(MROWS*H0 + 255)/256, 256>>>(cur12, s1, MROWS*H0, 0.5f);

    // fc2: 3-term spike GEMM (19968x512 -> 512)
    {
        Terms t2;
        t2.A[0]=s1; t2.B[0]=W1h;
        t2.A[1]=s1; t2.B[1]=W1m;
        t2.A[2]=s1; t2.B[2]=W1l;
        t2.A[3]=t2.A[4]=t2.A[5]=s1; t2.B[3]=t2.B[4]=t2.B[5]=W1h;
        kfc23<<<dim3(H1/128, MALL/128), 128, SMEM>>>(t2, b_h1, cur12, H1);
    }
    lif_scan_kernel<<<(MROWS*H1 + 255)/256, 256>>>(cur12, s2, MROWS*H1, 0.5f);

    // fc3: 3-term spike GEMM (19968x512 -> 256)
    {
        Terms t3;
        t3.A[0]=s2; t3.B[0]=W2h;
        t3.A[1]=s2; t3.B[1]=W2m;
        t3.A[2]=s2; t3.B[2]=W2l;
        t3.A[3]=t3.A[4]=t3.A[5]=s2; t3.B[3]=t3.B[4]=t3.B[5]=W2h;
        kfc23<<<dim3(H2/128, MALL/128), 128, SMEM>>>(t3, b_h2, cur3, H2);
    }
    lif_scan_kernel<<<(MROWS*H2 + 255)/256, 256>>>(cur3, s3, MROWS*H2, 0.5f);

    fcout_kernel<<<TSTEPS*BATCH, 256>>>(s3, W_out, b_out, curout);
    lifout_kernel<<<1, BATCH*NCLS>>>(curout, out);
}

// round 8
// speedup vs baseline: 3.2643x; 1.5069x over previous
#include <cuda_runtime.h>
#include <cuda_fp16.h>
#include <cstdint>
#include <cstddef>

typedef __half f16;

// ---------------- problem constants ----------------
#define TSTEPS 8
#define BATCH  64
#define CC     3
#define NWIN   232
#define HH     64
#define WW     64
#define CHUNK  29
#define DPP    13
#define INDIM  1024
#define H0     512
#define H1     512
#define H2     256
#define CD     39
#define FEAT   9984
#define NCLS   4
#define MROWS  (BATCH*CD)        // 2496
#define MALL   (TSTEPS*MROWS)    // 19968
#define BETA   0.9f

// ---------------- scratch (static device memory) ----------------
__device__ f16   g_A0[(size_t)MALL * INDIM];
__device__ f16   g_A1[(size_t)MALL * INDIM];
__device__ float g_cur1[(size_t)MALL * H0];      // reused for cur2
__device__ float g_cur3[(size_t)MALL * H2];
__device__ f16   g_s1[(size_t)MALL * H0];
__device__ f16   g_s2[(size_t)MALL * H1];
__device__ f16   g_s3[(size_t)MALL * H2];
__device__ float g_curout[TSTEPS * BATCH * NCLS];
__device__ f16 g_Wi0[H0 * INDIM], g_Wi1[H0 * INDIM];
__device__ f16 g_W10[H1 * H0],    g_W11[H1 * H0];
__device__ f16 g_W20[H2 * H1],    g_W21[H2 * H1];

// ---------------- fp32 -> 2x fp16 split (24-bit capture) ----------------
__device__ __forceinline__ void split2(float a, f16& h0, f16& h1) {
    h0 = __float2half_rn(a);
    float r = a - __half2float(h0);    // exact (error-free transform)
    h1 = __float2half_rn(r);           // residual <= 2^-24 |a| (or subnormal floor)
}

__global__ void wsplit_kernel(const float* __restrict__ w, int n,
                              f16* __restrict__ h0, f16* __restrict__ h1) {
    int i = blockIdx.x * blockDim.x + threadIdx.x;
    if (i >= n) return;
    f16 a, b;
    split2(w[i], a, b);
    h0[i] = a; h1[i] = b;
}

// ---------------- avg-pool3d fused with A-matrix 2-split ----------------
__global__ void pool_kernel(const float* __restrict__ x) {
    int idx = blockIdx.x * blockDim.x + threadIdx.x;
    if (idx >= MALL * INDIM) return;
    int hw = idx & (INDIM - 1);
    int r  = idx >> 10;
    int cd = r % CD;
    int tb = r / CD;
    int b  = tb % BATCH;
    int t  = tb / BATCH;
    int c  = cd / DPP;
    int dp = cd % DPP;
    int hp = hw >> 5;
    int wp = hw & 31;
    int d0 = t * CHUNK + 2 * dp;
    const float* base = x + (((size_t)b * CC + c) * NWIN) * (HH * WW)
                          + (size_t)(2 * hp) * WW + (size_t)(2 * wp);
    float s = 0.f;
#pragma unroll
    for (int kd = 0; kd < 4; kd++) {
        const float* p = base + (size_t)(d0 + kd) * (HH * WW);
        float2 r0 = *(const float2*)(p);
        float2 r1 = *(const float2*)(p + WW);
        s += (r0.x + r0.y) + (r1.x + r1.y);
    }
    s *= (1.0f / 16.0f);
    f16 h0, h1;
    split2(s, h0, h1);
    g_A0[idx] = h0; g_A1[idx] = h1;
}

// ---------------- cp.async / ldmatrix helpers ----------------
__device__ __forceinline__ void cpasync16(void* s, const void* g) {
    uint32_t sa = (uint32_t)__cvta_generic_to_shared(s);
    asm volatile("cp.async.cg.shared.global [%0], [%1], 16;\n" :: "r"(sa), "l"(g));
}
__device__ __forceinline__ void cp_commit() {
    asm volatile("cp.async.commit_group;\n");
}
template<int N> __device__ __forceinline__ void cp_wait() {
    asm volatile("cp.async.wait_group %0;\n" :: "n"(N));
}
__device__ __forceinline__ void ldmatrix_x4(uint32_t* r, const void* p) {
    uint32_t a = (uint32_t)__cvta_generic_to_shared(p);
    asm volatile("ldmatrix.sync.aligned.m8n8.x4.shared.b16 {%0,%1,%2,%3}, [%4];\n"
        : "=r"(r[0]), "=r"(r[1]), "=r"(r[2]), "=r"(r[3]) : "r"(a));
}

// ---------------- fp16 tensor-core multi-term GEMM, 3-stage pipeline ------
struct Terms {
    const f16* A[3];
    const f16* B[3];
};

__device__ __forceinline__ void mma16816(float* c, const uint32_t* a, const uint32_t* b) {
    asm volatile(
        "mma.sync.aligned.m16n8k16.row.col.f32.f16.f16.f32 "
        "{%0,%1,%2,%3},{%4,%5,%6,%7},{%8,%9},{%0,%1,%2,%3};\n"
        : "+f"(c[0]), "+f"(c[1]), "+f"(c[2]), "+f"(c[3])
        : "r"(a[0]), "r"(a[1]), "r"(a[2]), "r"(a[3]), "r"(b[0]), "r"(b[1]));
}

// BM=BN=128, BK=64, 4 warps, warp tile 64x64, 3-stage cp.async, 2 CTAs/SM.
template<int NT, int K>
__global__ void __launch_bounds__(128, 2)
mma_gemm(Terms terms, const float* __restrict__ bias,
         float* __restrict__ curOut, int N) {
    constexpr int BM = 128, BN = 128, BK = 64;
    constexpr int WM = 64,  WN = 64;
    constexpr int PAD = 8, LDW = BK + PAD;
    constexpr int STAGES = 3;
    constexpr int KT = K / BK;
    constexpr int NTILE = NT * KT;
    constexpr int MF = WM / 16, NF = WN / 8;   // 4, 8

    extern __shared__ char dynsmem[];
    f16 (*As)[BM][LDW] = (f16(*)[BM][LDW])dynsmem;
    f16 (*Bs)[BN][LDW] = (f16(*)[BN][LDW])(dynsmem + (size_t)STAGES * BM * LDW * 2);

    const int tid  = threadIdx.x;
    const int lane = tid & 31;
    const int warp = tid >> 5;
    const int g    = lane >> 2;
    const int tg   = lane & 3;
    const int wn0  = (warp & 1) * WN;
    const int wm0  = (warp >> 1) * WM;
    const int bm   = blockIdx.y * BM;
    const int bn   = blockIdx.x * BN;

    const int l8   = lane & 7;
    const int aRow = ((lane >> 3) & 1) * 8 + l8;
    const int aCol = (lane >> 4) * 8;
    const int bRow = (lane >> 4) * 8 + l8;
    const int bCol = ((lane >> 3) & 1) * 8;

    // loader: BK=64 -> 8 x 16B chunks per row; 128 threads -> 16 rows/pass
    const int lr = tid >> 3;
    const int lc = (tid & 7) * 8;

    auto load_tile = [&](int i, int s) {
        const int term = i / KT;
        const int k0   = (i % KT) * BK;
        const f16* __restrict__ Ag = terms.A[term] + (size_t)bm * K + k0;
        const f16* __restrict__ Bg = terms.B[term] + (size_t)bn * K + k0;
#pragma unroll
        for (int it = 0; it < 8; it++)
            cpasync16(&As[s][lr + it*16][lc], Ag + (size_t)(lr + it*16) * K + lc);
#pragma unroll
        for (int it = 0; it < 8; it++)
            cpasync16(&Bs[s][lr + it*16][lc], Bg + (size_t)(lr + it*16) * K + lc);
        cp_commit();
    };

    float acc[MF][NF][4];
#pragma unroll
    for (int i = 0; i < MF; i++)
#pragma unroll
        for (int j = 0; j < NF; j++)
#pragma unroll
            for (int q = 0; q < 4; q++) acc[i][j][q] = 0.f;

#pragma unroll
    for (int i = 0; i < STAGES - 1; i++) load_tile(i, i);

    for (int i = 0; i < NTILE; i++) {
        cp_wait<STAGES - 2>();
        __syncthreads();
        const int nxt = i + STAGES - 1;
        if (nxt < NTILE) load_tile(nxt, nxt % STAGES);
        const int st = i % STAGES;
#pragma unroll
        for (int ks = 0; ks < BK; ks += 16) {
            uint32_t fa[MF][4], fb[NF][2];
#pragma unroll
            for (int mf = 0; mf < MF; mf++)
                ldmatrix_x4(fa[mf], &As[st][wm0 + mf*16 + aRow][ks + aCol]);
#pragma unroll
            for (int p = 0; p < NF/2; p++) {
                uint32_t r[4];
                ldmatrix_x4(r, &Bs[st][wn0 + p*16 + bRow][ks + bCol]);
                fb[2*p  ][0] = r[0]; fb[2*p  ][1] = r[1];
                fb[2*p+1][0] = r[2]; fb[2*p+1][1] = r[3];
            }
#pragma unroll
            for (int mf = 0; mf < MF; mf++)
#pragma unroll
                for (int nf = 0; nf < NF; nf++)
                    mma16816(acc[mf][nf], fa[mf], fb[nf]);
        }
    }

    // epilogue: fp32 currents + bias
#pragma unroll
    for (int mf = 0; mf < MF; mf++) {
#pragma unroll
        for (int nf = 0; nf < NF; nf++) {
            int m0 = bm + wm0 + mf*16 + g;
            int n0 = bn + wn0 + nf*8 + 2*tg;
#pragma unroll
            for (int q = 0; q < 4; q++) {
                int m = m0 + (q >> 1) * 8;
                int n = n0 + (q & 1);
                curOut[(size_t)m * N + n] = acc[mf][nf][q] + bias[n];
            }
        }
    }
}

// ---------------- LIF time-scan: membrane in register, 8 steps ------------
__global__ void lif_scan_kernel(const float* __restrict__ cur,
                                f16* __restrict__ spk, int n, float thr) {
    int i = blockIdx.x * blockDim.x + threadIdx.x;
    if (i >= n) return;
    float m = 0.f;
#pragma unroll
    for (int t = 0; t < TSTEPS; t++) {
        float reset = (m > thr) ? thr : 0.f;
        m = BETA * m + cur[(size_t)t * n + i] - reset;
        spk[(size_t)t * n + i] = __float2half_rn((m - thr) > 0.f ? 1.f : 0.f);
    }
}

// ---------------- readout currents: (t,b) row x Wout (4 x 9984) ----------
__global__ void fcout_kernel(const f16* __restrict__ s3,
                             const float* __restrict__ Wout,
                             const float* __restrict__ bout,
                             float* __restrict__ curout) {
    const int tb  = blockIdx.x;          // t*BATCH + b
    const int t   = tb / BATCH;
    const int b   = tb % BATCH;
    const int tid = threadIdx.x;         // 256
    const f16* sp = s3 + ((size_t)t * MROWS + (size_t)b * CD) * H2;
    float a0 = 0.f, a1 = 0.f, a2 = 0.f, a3 = 0.f;
    for (int k = tid; k < FEAT; k += 256) {
        if (__half2float(sp[k]) != 0.f) {
            a0 += Wout[0 * FEAT + k];
            a1 += Wout[1 * FEAT + k];
            a2 += Wout[2 * FEAT + k];
            a3 += Wout[3 * FEAT + k];
        }
    }
    __shared__ float red[4][256];
    red[0][tid] = a0; red[1][tid] = a1; red[2][tid] = a2; red[3][tid] = a3;
    __syncthreads();
    for (int st = 128; st > 0; st >>= 1) {
        if (tid < st) {
#pragma unroll
            for (int n = 0; n < 4; n++) red[n][tid] += red[n][tid + st];
        }
        __syncthreads();
    }
    if (tid < NCLS)
        curout[(size_t)tb * NCLS + tid] = red[tid][0] + bout[tid];
}

// ---------------- output LIF scan (thr = 1.0) ----------------------------
__global__ void lifout_kernel(const float* __restrict__ curout,
                              float* __restrict__ out) {
    int i = threadIdx.x;                 // BATCH*NCLS = 256
    float m = 0.f;
#pragma unroll
    for (int t = 0; t < TSTEPS; t++) {
        float reset = (m > 1.0f) ? 1.0f : 0.f;
        m = BETA * m + curout[t * BATCH * NCLS + i] - reset;
        out[t * BATCH * NCLS + i] = (m - 1.0f) > 0.f ? 1.f : 0.f;
    }
}

// ---------------- host orchestration ----------------
extern "C" void kernel_launch(void* const* d_in, const int* in_sizes, int n_in,
                              void* d_out, int out_size) {
    const float* x     = (const float*)d_in[0];
    const float* W_in  = (const float*)d_in[1];
    const float* b_in  = (const float*)d_in[2];
    const float* W_h1  = (const float*)d_in[3];
    const float* b_h1  = (const float*)d_in[4];
    const float* W_h2  = (const float*)d_in[5];
    const float* b_h2  = (const float*)d_in[6];
    const float* W_out = (const float*)d_in[7];
    const float* b_out = (const float*)d_in[8];
    float* out = (float*)d_out;

    f16 *A0, *A1, *s1, *s2, *s3;
    f16 *Wi0, *Wi1, *W10, *W11, *W20, *W21;
    float *cur12, *cur3, *curout;
    cudaGetSymbolAddress((void**)&A0, g_A0);
    cudaGetSymbolAddress((void**)&A1, g_A1);
    cudaGetSymbolAddress((void**)&cur12, g_cur1);
    cudaGetSymbolAddress((void**)&cur3, g_cur3);
    cudaGetSymbolAddress((void**)&curout, g_curout);
    cudaGetSymbolAddress((void**)&s1, g_s1);
    cudaGetSymbolAddress((void**)&s2, g_s2);
    cudaGetSymbolAddress((void**)&s3, g_s3);
    cudaGetSymbolAddress((void**)&Wi0, g_Wi0);
    cudaGetSymbolAddress((void**)&Wi1, g_Wi1);
    cudaGetSymbolAddress((void**)&W10, g_W10);
    cudaGetSymbolAddress((void**)&W11, g_W11);
    cudaGetSymbolAddress((void**)&W20, g_W20);
    cudaGetSymbolAddress((void**)&W21, g_W21);

    // smem: 3 stages * (128 + 128) rows * 72 elems * 2B = 110592
    constexpr int SMEM = 3 * (128 + 128) * 72 * 2;
    auto kfc1 = mma_gemm<3, 1024>;
    auto kfc23 = mma_gemm<2, 512>;
    cudaFuncSetAttribute(kfc1,  cudaFuncAttributeMaxDynamicSharedMemorySize, SMEM);
    cudaFuncSetAttribute(kfc23, cudaFuncAttributeMaxDynamicSharedMemorySize, SMEM);

    wsplit_kernel<<<(H0*INDIM + 255)/256, 256>>>(W_in, H0*INDIM, Wi0, Wi1);
    wsplit_kernel<<<(H1*H0   + 255)/256, 256>>>(W_h1, H1*H0,   W10, W11);
    wsplit_kernel<<<(H2*H1   + 255)/256, 256>>>(W_h2, H2*H1,   W20, W21);

    pool_kernel<<<(MALL*INDIM + 255)/256, 256>>>(x);

    // fc1: 3-term fp16 split GEMM (19968x1024 -> 512)
    // (a0+a1)(w0+w1) ~= a0w0 + a0w1 + a1w0  (a1w1 <= 2^-24 rel, dropped)
    {
        Terms t1;
        t1.A[0]=A0; t1.B[0]=Wi0;
        t1.A[1]=A0; t1.B[1]=Wi1;
        t1.A[2]=A1; t1.B[2]=Wi0;
        kfc1<<<dim3(H0/128, MALL/128), 128, SMEM>>>(t1, b_in, cur12, H0);
    }
    lif_scan_kernel<<<(MROWS*H0 + 255)/256, 256>>>(cur12, s1, MROWS*H0, 0.5f);

    // fc2: 2-term spike GEMM (19968x512 -> 512); spikes exact in fp16
    {
        Terms t2;
        t2.A[0]=s1; t2.B[0]=W10;
        t2.A[1]=s1; t2.B[1]=W11;
        t2.A[2]=s1; t2.B[2]=W10;   // unused (NT=2)
        kfc23<<<dim3(H1/128, MALL/128), 128, SMEM>>>(t2, b_h1, cur12, H1);
    }
    lif_scan_kernel<<<(MROWS*H1 + 255)/256, 256>>>(cur12, s2, MROWS*H1, 0.5f);

    // fc3: 2-term spike GEMM (19968x512 -> 256)
    {
        Terms t3;
        t3.A[0]=s2; t3.B[0]=W20;
        t3.A[1]=s2; t3.B[1]=W21;
        t3.A[2]=s2; t3.B[2]=W20;   // unused (NT=2)
        kfc23<<<dim3(H2/128, MALL/128), 128, SMEM>>>(t3, b_h2, cur3, H2);
    }
    lif_scan_kernel<<<(MROWS*H2 + 255)/256, 256>>>(cur3, s3, MROWS*H2, 0.5f);

    fcout_kernel<<<TSTEPS*BATCH, 256>>>(s3, W_out, b_out, curout);
    lifout_kernel<<<1, BATCH*NCLS>>>(curout, out);
}